// round 6
// baseline (speedup 1.0000x reference)
#include <cuda_runtime.h>
#include <math.h>

#define N_SRC  80000
#define N_TGT  20000
#define E_NUM  80000
#define IN_DIM 128
#define DIM    64
#define EH     128
#define G3     192
#define NK     129   // up to 128 breakpoints -> 129 intervals
#define MAXU   2     // intervals cached in fast path (fallback covers the rest)

typedef unsigned long long ull;

// ---------------- f32x2 helpers ------------------------------------------
__device__ __forceinline__ ull pk2(float lo, float hi) {
    ull r; asm("mov.b64 %0, {%1,%2};" : "=l"(r) : "f"(lo), "f"(hi)); return r;
}
__device__ __forceinline__ void upk(ull v, float& lo, float& hi) {
    asm("mov.b64 {%0,%1}, %2;" : "=f"(lo), "=f"(hi) : "l"(v));
}
#define FMA_X2(d, a, b, c) asm("fma.rn.f32x2 %0, %1, %2, %3;" : "=l"(d) : "l"(a), "l"(b), "l"(c))

__device__ __forceinline__ float sigm(float x)  { return __fdividef(1.0f, 1.0f + __expf(-x)); }
__device__ __forceinline__ float tanhx(float x) { return 1.0f - __fdividef(2.0f, 1.0f + __expf(2.0f * x)); }

// ---------------- scratch (device globals; no allocation) ----------------
__device__ float g_h0[N_SRC * DIM];
__device__ float g_M[NK][DIM * DIM];
__device__ float g_P[NK][DIM * DIM];
__device__ float g_thr[EH];
__device__ unsigned char g_act[NK][EH];
__device__ int   g_kedge[E_NUM];
__device__ float g_aedge[E_NUM];
__device__ int   g_used[NK];
__device__ int   g_slotmap[NK];
__device__ int   g_slotk[MAXU];
__device__ int   g_usedlist[NK];
__device__ int   g_usedcnt;
__device__ int   g_nslots;
__device__ int   g_deg[N_TGT];
__device__ int   g_off[N_TGT];
__device__ int   g_cur[N_TGT];
__device__ unsigned g_cw[E_NUM];
__device__ float g_ca[E_NUM];
__device__ float g_W0t[IN_DIM * DIM];
__device__ ull   g_Wih_d[DIM * G3];
__device__ ull   g_Whh_d[DIM * G3];
__device__ ull   g_Wr_d[DIM * DIM];
__device__ ull   g_W1d[DIM * DIM];
__device__ ull   g_W2d[DIM * DIM];

// ---------------- zero scratch -------------------------------------------
__global__ void k_zero() {
    int idx = blockIdx.x * blockDim.x + threadIdx.x;
    if (idx < N_TGT) g_deg[idx] = 0;
    if (idx < NK)    g_used[idx] = 0;
}

// ---------------- weight prep: transpose + f32x2-dup tables --------------
__global__ void k_prep(const float* __restrict__ W0, const float* __restrict__ Wih,
                       const float* __restrict__ Whh, const float* __restrict__ Wr,
                       const float* __restrict__ W1, const float* __restrict__ W2) {
    int idx = blockIdx.x * blockDim.x + threadIdx.x;
    if (idx < IN_DIM * DIM) {            // W0t[i*64+o] = W0[o*128+i]
        int i = idx / DIM, o = idx % DIM;
        g_W0t[idx] = W0[o * IN_DIM + i];
    }
    if (idx < DIM * G3) {                // [o][g] dup tables
        int o = idx / G3, g = idx % G3;
        float wi = Wih[g * DIM + o]; g_Wih_d[idx] = pk2(wi, wi);
        float wh = Whh[g * DIM + o]; g_Whh_d[idx] = pk2(wh, wh);
    }
    if (idx < DIM * DIM) {
        int i = idx / DIM, o = idx % DIM;
        float wr = Wr[idx];          g_Wr_d[idx] = pk2(wr, wr);
        float w1 = W1[o * DIM + i];  g_W1d[idx] = pk2(w1, w1);
        float w2 = W2[o * DIM + i];  g_W2d[idx] = pk2(w2, w2);
    }
}

// ---------------- sort breakpoints, build active masks -------------------
__global__ void k_setup(const float* __restrict__ A1, const float* __restrict__ c1) {
    __shared__ float ts[EH], sorted[EH];
    int j = threadIdx.x;
    float s = A1[j];
    float c = c1[j];
    float t = (s != 0.0f) ? (-c / s) : 2.0e30f;
    ts[j] = t;
    __syncthreads();
    int rank = 0;
    for (int k = 0; k < EH; k++) {
        float tk = ts[k];
        rank += (tk < t) || (tk == t && k < j);
    }
    sorted[rank] = t;
    __syncthreads();
    g_thr[j] = sorted[j];
    const float BIGT = 1.0e29f;
    for (int k = 0; k < NK; k++) {
        float left  = (k > 0)  ? sorted[k - 1] : -2.0e30f;
        float right = (k < EH) ? sorted[k]     :  2.0e30f;
        bool linf = (left <= -BIGT), rinf = (right >= BIGT);
        float rep;
        if (linf && rinf)      rep = 0.0f;
        else if (linf)         rep = right - 1.0f;
        else if (rinf)         rep = left + 1.0f;
        else                   rep = 0.5f * (left + right);
        g_act[k][j] = (s * rep + c > 0.0f) ? 1 : 0;
    }
}

// ---------------- per-edge scalar + interval id + degree -----------------
__global__ void k_edgek(const int* __restrict__ eids, const float* __restrict__ ew,
                        const int* __restrict__ edst) {
    __shared__ float thr[EH];
    if (threadIdx.x < EH) thr[threadIdx.x] = g_thr[threadIdx.x];
    __syncthreads();
    int e = blockIdx.x * blockDim.x + threadIdx.x;
    if (e >= E_NUM) return;
    float a = ew[eids[e]];
    int k = 0;
#pragma unroll
    for (int j = 0; j < EH; j++) k += (thr[j] < a) ? 1 : 0;
    g_kedge[e] = k;
    g_aedge[e] = a;
    g_used[k]  = 1;
    atomicAdd(&g_deg[edst[e]], 1);
}

// ---------------- slot assignment + compact used list --------------------
__global__ void k_slots() {
    __shared__ int u[NK];
    for (int k = threadIdx.x; k < NK; k += 128) {
        u[k] = g_used[k];
        g_slotmap[k] = -1;
    }
    __syncthreads();
    if (threadIdx.x == 0) {
        int ns = 0;
        for (int k = 0; k < NK; k++) {
            if (u[k]) {
                if (ns < MAXU) { g_slotmap[k] = ns; g_slotk[ns] = k; }
                g_usedlist[ns] = k;
                ns++;
            }
        }
        g_usedcnt = ns;
        g_nslots = (ns < MAXU) ? ns : MAXU;
    }
}

// ---------------- exclusive scan of degrees -> CSR offsets ---------------
__global__ __launch_bounds__(1024) void k_scan() {
    __shared__ int wsum[32];
    int t = threadIdx.x;
    int start = t * 20;
    int s = 0;
#pragma unroll
    for (int i = 0; i < 20; i++) {
        int idx = start + i;
        if (idx < N_TGT) s += g_deg[idx];
    }
    int lane = t & 31, wid = t >> 5;
    int v = s;
#pragma unroll
    for (int off = 1; off < 32; off <<= 1) {
        int n = __shfl_up_sync(0xffffffffu, v, off);
        if (lane >= off) v += n;
    }
    if (lane == 31) wsum[wid] = v;
    __syncthreads();
    if (wid == 0) {
        int w = wsum[lane];
#pragma unroll
        for (int off = 1; off < 32; off <<= 1) {
            int n = __shfl_up_sync(0xffffffffu, w, off);
            if (lane >= off) w += n;
        }
        wsum[lane] = w;
    }
    __syncthreads();
    int excl = (v - s) + ((wid > 0) ? wsum[wid - 1] : 0);
    int run = excl;
#pragma unroll
    for (int i = 0; i < 20; i++) {
        int idx = start + i;
        if (idx < N_TGT) {
            g_off[idx] = run;
            g_cur[idx] = run;
            run += g_deg[idx];
        }
    }
}

// ---------------- build M_k / P_k only for used intervals ----------------
// grid (512, 8); each block strides over the compacted used list.
__global__ void k_tables(const float* __restrict__ A1, const float* __restrict__ c1,
                         const float* __restrict__ A2, const float* __restrict__ c2) {
    __shared__ float hs[EH], h2s[EH];
    int cnt = g_usedcnt;
    int t = threadIdx.x;
    for (int y = blockIdx.y; y < cnt; y += 8) {
        int k = g_usedlist[y];
        __syncthreads();
        if (t < EH) {
            float a = g_act[k][t] ? 1.0f : 0.0f;
            hs[t]  = A1[t] * a;
            h2s[t] = c1[t] * a;
        }
        __syncthreads();
        int w = t >> 5, l = t & 31;
        int io = blockIdx.x * 8 + w;
        const float4 av = *reinterpret_cast<const float4*>(A2 + (size_t)io * EH + l * 4);
        float m = av.x * hs[l * 4] + av.y * hs[l * 4 + 1] + av.z * hs[l * 4 + 2] + av.w * hs[l * 4 + 3];
        float p = av.x * h2s[l * 4] + av.y * h2s[l * 4 + 1] + av.z * h2s[l * 4 + 2] + av.w * h2s[l * 4 + 3];
#pragma unroll
        for (int off = 16; off > 0; off >>= 1) {
            m += __shfl_down_sync(0xffffffffu, m, off);
            p += __shfl_down_sync(0xffffffffu, p, off);
        }
        if (l == 0) {
            g_M[k][io] = m;
            g_P[k][io] = c2[io] + p;
        }
    }
}

// ---------------- CSR placement ------------------------------------------
__global__ void k_csr(const int* __restrict__ esrc, const int* __restrict__ edst) {
    int e = blockIdx.x * blockDim.x + threadIdx.x;
    if (e >= E_NUM) return;
    int dst = edst[e];
    int pos = atomicAdd(&g_cur[dst], 1);
    int k = g_kedge[e];
    int sm = g_slotmap[k];
    unsigned sc = (sm >= 0) ? (unsigned)sm : 7u;
    g_cw[pos] = (unsigned)esrc[e] | ((unsigned)k << 17) | (sc << 25);
    g_ca[pos] = g_aedge[e];
}

// ---------------- h0 = relu(x @ W0^T + b0), FFMA2 ------------------------
__global__ __launch_bounds__(256) void k_h0(const float* __restrict__ x,
                                            const float* __restrict__ b0) {
    int j  = threadIdx.x & 31;          // output pair index
    int gq = threadIdx.x >> 5;          // 0..7
    int row0 = blockIdx.x * 32 + gq * 4;
    ull acc[4] = {0ull, 0ull, 0ull, 0ull};
    const ull* __restrict__ W = reinterpret_cast<const ull*>(g_W0t);
#pragma unroll 4
    for (int ii = 0; ii < IN_DIM / 4; ii++) {
        float4 xv0 = *reinterpret_cast<const float4*>(x + (size_t)(row0 + 0) * IN_DIM + ii * 4);
        float4 xv1 = *reinterpret_cast<const float4*>(x + (size_t)(row0 + 1) * IN_DIM + ii * 4);
        float4 xv2 = *reinterpret_cast<const float4*>(x + (size_t)(row0 + 2) * IN_DIM + ii * 4);
        float4 xv3 = *reinterpret_cast<const float4*>(x + (size_t)(row0 + 3) * IN_DIM + ii * 4);
#define H0_STEP(comp, s)                                               \
        {                                                              \
            ull wv = W[(ii * 4 + s) * 32 + j];                         \
            FMA_X2(acc[0], pk2(xv0.comp, xv0.comp), wv, acc[0]);       \
            FMA_X2(acc[1], pk2(xv1.comp, xv1.comp), wv, acc[1]);       \
            FMA_X2(acc[2], pk2(xv2.comp, xv2.comp), wv, acc[2]);       \
            FMA_X2(acc[3], pk2(xv3.comp, xv3.comp), wv, acc[3]);       \
        }
        H0_STEP(x, 0) H0_STEP(y, 1) H0_STEP(z, 2) H0_STEP(w, 3)
#undef H0_STEP
    }
    float ba = b0[2 * j], bb = b0[2 * j + 1];
#pragma unroll
    for (int r = 0; r < 4; r++) {
        float lo, hi;
        upk(acc[r], lo, hi);
        float2 v;
        v.x = fmaxf(lo + ba, 0.0f);
        v.y = fmaxf(hi + bb, 0.0f);
        *reinterpret_cast<float2*>(g_h0 + (size_t)(row0 + r) * DIM + 2 * j) = v;
    }
}

// ---------------- MEGA: gather + transform + conv + gi + GRU + head ------
// warp handles 4 consecutive targets; dynamic smem holds M/P for the slots.
__global__ __launch_bounds__(256) void k_mega(const float* __restrict__ b_conv,
                                              const float* __restrict__ b_ih,
                                              const float* __restrict__ b_hh,
                                              const float* __restrict__ b1,
                                              const float* __restrict__ b2,
                                              float* __restrict__ out) {
    extern __shared__ float smp[];      // [slot][ M:4096 | P:4096 ]
    int ns = g_nslots;
    // cooperative fill of table cache
    for (int s = 0; s < ns; s++) {
        const float4* Mg = reinterpret_cast<const float4*>(g_M[g_slotk[s]]);
        const float4* Pg = reinterpret_cast<const float4*>(g_P[g_slotk[s]]);
        float4* dM = reinterpret_cast<float4*>(smp + s * 8192);
        float4* dP = reinterpret_cast<float4*>(smp + s * 8192 + 4096);
        for (int idx = threadIdx.x; idx < DIM * DIM / 4; idx += 256) {
            dM[idx] = Mg[idx];
            dP[idx] = Pg[idx];
        }
    }
    __syncthreads();

    int gw = (blockIdx.x * 256 + threadIdx.x) >> 5;
    int l  = threadIdx.x & 31;
    int r0 = gw * 4;
    if (r0 >= N_TGT) return;

    // ---- edge gather ----
    int offv[4], degv[4];
#pragma unroll
    for (int q = 0; q < 4; q++) { offv[q] = g_off[r0 + q]; degv[q] = g_deg[r0 + q]; }
    int dmax = max(max(degv[0], degv[1]), max(degv[2], degv[3]));

    float S0a[MAXU][4], S0b[MAXU][4], S1a[MAXU][4], S1b[MAXU][4];
#pragma unroll
    for (int s = 0; s < MAXU; s++)
#pragma unroll
        for (int q = 0; q < 4; q++) { S0a[s][q] = 0; S0b[s][q] = 0; S1a[s][q] = 0; S1b[s][q] = 0; }
    float fbA[4] = {0, 0, 0, 0}, fbB[4] = {0, 0, 0, 0};

    for (int j = 0; j < dmax; j++) {
#pragma unroll
        for (int q = 0; q < 4; q++) {
            if (j < degv[q]) {                       // warp-uniform
                int pos = offv[q] + j;
                unsigned w = g_cw[pos];
                float a = g_ca[pos];
                int src = (int)(w & 0x1FFFFu);
                unsigned sc = w >> 25;
                const float* __restrict__ hrow = g_h0 + (size_t)src * DIM;
                float xs0 = hrow[l], xs1 = hrow[32 + l];
                float ax0 = a * xs0, ax1 = a * xs1;
#pragma unroll
                for (int s = 0; s < MAXU; s++) {
                    float sel = (sc == (unsigned)s) ? 1.0f : 0.0f;
                    S0a[s][q] += sel * xs0; S0b[s][q] += sel * xs1;
                    S1a[s][q] += sel * ax0; S1b[s][q] += sel * ax1;
                }
                if (sc == 7u) {                      // exact fallback (rare)
                    int k = (int)((w >> 17) & 0xFFu);
                    const float* __restrict__ M = g_M[k];
                    const float* __restrict__ P = g_P[k];
#pragma unroll 8
                    for (int i = 0; i < DIM; i++) {
                        float xi  = __shfl_sync(0xffffffffu, (i < 32) ? xs0 : xs1, i & 31);
                        float axi = a * xi;
                        fbA[q] += axi * M[i * DIM + l]      + xi * P[i * DIM + l];
                        fbB[q] += axi * M[i * DIM + 32 + l] + xi * P[i * DIM + 32 + l];
                    }
                }
            }
        }
    }

    // ---- transform: agg = fallback + sum_s S1_s@M_s + S0_s@P_s ----
    ull accA[2], accB[2];
    accA[0] = pk2(fbA[0], fbA[1]); accA[1] = pk2(fbA[2], fbA[3]);
    accB[0] = pk2(fbB[0], fbB[1]); accB[1] = pk2(fbB[2], fbB[3]);
#pragma unroll
    for (int s = 0; s < MAXU; s++) {
        if (s >= ns) break;
        const float* __restrict__ sM = smp + s * 8192;
        const float* __restrict__ sP = sM + 4096;
#pragma unroll 4
        for (int i = 0; i < DIM; i++) {
            float m0 = sM[i * DIM + l], m1 = sM[i * DIM + 32 + l];
            float p0 = sP[i * DIM + l], p1 = sP[i * DIM + 32 + l];
            float t1[4], t0[4];
#pragma unroll
            for (int q = 0; q < 4; q++) {
                t1[q] = __shfl_sync(0xffffffffu, (i < 32) ? S1a[s][q] : S1b[s][q], i & 31);
                t0[q] = __shfl_sync(0xffffffffu, (i < 32) ? S0a[s][q] : S0b[s][q], i & 31);
            }
            ull s1p01 = pk2(t1[0], t1[1]), s1p23 = pk2(t1[2], t1[3]);
            ull s0p01 = pk2(t0[0], t0[1]), s0p23 = pk2(t0[2], t0[3]);
            ull m0p = pk2(m0, m0), m1p = pk2(m1, m1);
            ull p0p = pk2(p0, p0), p1p = pk2(p1, p1);
            FMA_X2(accA[0], s1p01, m0p, accA[0]); FMA_X2(accA[0], s0p01, p0p, accA[0]);
            FMA_X2(accA[1], s1p23, m0p, accA[1]); FMA_X2(accA[1], s0p23, p0p, accA[1]);
            FMA_X2(accB[0], s1p01, m1p, accB[0]); FMA_X2(accB[0], s0p01, p1p, accB[0]);
            FMA_X2(accB[1], s1p23, m1p, accB[1]); FMA_X2(accB[1], s0p23, p1p, accB[1]);
        }
    }

    // ---- m = relu(agg/cnt + x_tgt@W_root + b_conv) ----
    float xt0[4], xt1[4];
    ull mA[2], mB[2];
    {
        float invq[4];
#pragma unroll
        for (int q = 0; q < 4; q++) {
            xt0[q] = g_h0[(size_t)(r0 + q) * DIM + l];
            xt1[q] = g_h0[(size_t)(r0 + q) * DIM + 32 + l];
            invq[q] = __fdividef(1.0f, fmaxf((float)degv[q], 1.0f));
        }
        float v0, v1;
        upk(accA[0], v0, v1); mA[0] = pk2(v0 * invq[0], v1 * invq[1]);
        upk(accA[1], v0, v1); mA[1] = pk2(v0 * invq[2], v1 * invq[3]);
        upk(accB[0], v0, v1); mB[0] = pk2(v0 * invq[0], v1 * invq[1]);
        upk(accB[1], v0, v1); mB[1] = pk2(v0 * invq[2], v1 * invq[3]);
    }
#pragma unroll 4
    for (int i = 0; i < DIM; i++) {
        ull wv0 = g_Wr_d[i * DIM + l];
        ull wv1 = g_Wr_d[i * DIM + 32 + l];
        float xq[4];
#pragma unroll
        for (int q = 0; q < 4; q++)
            xq[q] = __shfl_sync(0xffffffffu, (i < 32) ? xt0[q] : xt1[q], i & 31);
        ull xp01 = pk2(xq[0], xq[1]), xp23 = pk2(xq[2], xq[3]);
        FMA_X2(mA[0], xp01, wv0, mA[0]); FMA_X2(mA[1], xp23, wv0, mA[1]);
        FMA_X2(mB[0], xp01, wv1, mB[0]); FMA_X2(mB[1], xp23, wv1, mB[1]);
    }
    float m0[4], m1[4];
    {
        float bc0 = b_conv[l], bc1 = b_conv[32 + l];
        float v0, v1;
        upk(mA[0], v0, v1); m0[0] = fmaxf(v0 + bc0, 0.0f); m0[1] = fmaxf(v1 + bc0, 0.0f);
        upk(mA[1], v0, v1); m0[2] = fmaxf(v0 + bc0, 0.0f); m0[3] = fmaxf(v1 + bc0, 0.0f);
        upk(mB[0], v0, v1); m1[0] = fmaxf(v0 + bc1, 0.0f); m1[1] = fmaxf(v1 + bc1, 0.0f);
        upk(mB[1], v0, v1); m1[2] = fmaxf(v0 + bc1, 0.0f); m1[3] = fmaxf(v1 + bc1, 0.0f);
    }

    // ---- gi = m @ W_ih^T + b_ih ----
    ull gip[6][2];
#pragma unroll
    for (int t = 0; t < 6; t++) { gip[t][0] = 0ull; gip[t][1] = 0ull; }
#pragma unroll 2
    for (int o = 0; o < DIM; o++) {
        float mq[4];
#pragma unroll
        for (int q = 0; q < 4; q++)
            mq[q] = __shfl_sync(0xffffffffu, (o < 32) ? m0[q] : m1[q], o & 31);
        ull mp01 = pk2(mq[0], mq[1]), mp23 = pk2(mq[2], mq[3]);
#pragma unroll
        for (int t = 0; t < 6; t++) {
            ull wv = g_Wih_d[o * G3 + l + 32 * t];
            FMA_X2(gip[t][0], mp01, wv, gip[t][0]);
            FMA_X2(gip[t][1], mp23, wv, gip[t][1]);
        }
    }
    float gi[6][4];
#pragma unroll
    for (int t = 0; t < 6; t++) {
        float bi = b_ih[l + 32 * t];
        float v0, v1;
        upk(gip[t][0], v0, v1); gi[t][0] = v0 + bi; gi[t][1] = v1 + bi;
        upk(gip[t][1], v0, v1); gi[t][2] = v0 + bi; gi[t][3] = v1 + bi;
    }

    // ---- GRU x3 (h init = x_tgt) ----
    float h0r[4], h1r[4];
#pragma unroll
    for (int q = 0; q < 4; q++) { h0r[q] = xt0[q]; h1r[q] = xt1[q]; }
    float bh[6];
#pragma unroll
    for (int t = 0; t < 6; t++) bh[t] = b_hh[l + 32 * t];

    for (int step = 0; step < 3; step++) {
        ull ghp[6][2];
#pragma unroll
        for (int t = 0; t < 6; t++) {
            ghp[t][0] = pk2(bh[t], bh[t]);
            ghp[t][1] = ghp[t][0];
        }
#pragma unroll 2
        for (int i = 0; i < DIM; i++) {
            float hq[4];
#pragma unroll
            for (int q = 0; q < 4; q++)
                hq[q] = __shfl_sync(0xffffffffu, (i < 32) ? h0r[q] : h1r[q], i & 31);
            ull hp01 = pk2(hq[0], hq[1]), hp23 = pk2(hq[2], hq[3]);
#pragma unroll
            for (int t = 0; t < 6; t++) {
                ull wv = g_Whh_d[i * G3 + l + 32 * t];
                FMA_X2(ghp[t][0], hp01, wv, ghp[t][0]);
                FMA_X2(ghp[t][1], hp23, wv, ghp[t][1]);
            }
        }
#pragma unroll
        for (int q = 0; q < 4; q++) {
            float ghv[6];
#pragma unroll
            for (int t = 0; t < 6; t++) {
                float lo, hi;
                upk(ghp[t][q >> 1], lo, hi);
                ghv[t] = (q & 1) ? hi : lo;
            }
            float rr0 = sigm(gi[0][q] + ghv[0]);
            float rr1 = sigm(gi[1][q] + ghv[1]);
            float zz0 = sigm(gi[2][q] + ghv[2]);
            float zz1 = sigm(gi[3][q] + ghv[3]);
            float nn0 = tanhx(gi[4][q] + rr0 * ghv[4]);
            float nn1 = tanhx(gi[5][q] + rr1 * ghv[5]);
            h0r[q] = (1.0f - zz0) * nn0 + zz0 * h0r[q];
            h1r[q] = (1.0f - zz1) * nn1 + zz1 * h1r[q];
        }
    }

    // ---- head: a = relu(h @ W1^T + b1); out = a @ W2^T + b2 ----
    ull aA01 = 0ull, aA23 = 0ull, aB01 = 0ull, aB23 = 0ull;
#pragma unroll 4
    for (int i = 0; i < DIM; i++) {
        float hq[4];
#pragma unroll
        for (int q = 0; q < 4; q++)
            hq[q] = __shfl_sync(0xffffffffu, (i < 32) ? h0r[q] : h1r[q], i & 31);
        ull hp01 = pk2(hq[0], hq[1]), hp23 = pk2(hq[2], hq[3]);
        ull wv0 = g_W1d[i * DIM + l], wv1 = g_W1d[i * DIM + 32 + l];
        FMA_X2(aA01, hp01, wv0, aA01); FMA_X2(aA23, hp23, wv0, aA23);
        FMA_X2(aB01, hp01, wv1, aB01); FMA_X2(aB23, hp23, wv1, aB23);
    }
    float a0[4], a1[4];
    {
        float bb0 = b1[l], bb1 = b1[32 + l];
        float v0, v1;
        upk(aA01, v0, v1); a0[0] = fmaxf(v0 + bb0, 0.0f); a0[1] = fmaxf(v1 + bb0, 0.0f);
        upk(aA23, v0, v1); a0[2] = fmaxf(v0 + bb0, 0.0f); a0[3] = fmaxf(v1 + bb0, 0.0f);
        upk(aB01, v0, v1); a1[0] = fmaxf(v0 + bb1, 0.0f); a1[1] = fmaxf(v1 + bb1, 0.0f);
        upk(aB23, v0, v1); a1[2] = fmaxf(v0 + bb1, 0.0f); a1[3] = fmaxf(v1 + bb1, 0.0f);
    }
    ull cA01 = 0ull, cA23 = 0ull, cB01 = 0ull, cB23 = 0ull;
#pragma unroll 4
    for (int i = 0; i < DIM; i++) {
        float aq[4];
#pragma unroll
        for (int q = 0; q < 4; q++)
            aq[q] = __shfl_sync(0xffffffffu, (i < 32) ? a0[q] : a1[q], i & 31);
        ull ap01 = pk2(aq[0], aq[1]), ap23 = pk2(aq[2], aq[3]);
        ull wv0 = g_W2d[i * DIM + l], wv1 = g_W2d[i * DIM + 32 + l];
        FMA_X2(cA01, ap01, wv0, cA01); FMA_X2(cA23, ap23, wv0, cA23);
        FMA_X2(cB01, ap01, wv1, cB01); FMA_X2(cB23, ap23, wv1, cB23);
    }
    {
        float ob0 = b2[l], ob1 = b2[32 + l];
        float v0, v1;
        upk(cA01, v0, v1);
        out[(size_t)(r0 + 0) * DIM + l] = v0 + ob0;
        out[(size_t)(r0 + 1) * DIM + l] = v1 + ob0;
        upk(cA23, v0, v1);
        out[(size_t)(r0 + 2) * DIM + l] = v0 + ob0;
        out[(size_t)(r0 + 3) * DIM + l] = v1 + ob0;
        upk(cB01, v0, v1);
        out[(size_t)(r0 + 0) * DIM + 32 + l] = v0 + ob1;
        out[(size_t)(r0 + 1) * DIM + 32 + l] = v1 + ob1;
        upk(cB23, v0, v1);
        out[(size_t)(r0 + 2) * DIM + 32 + l] = v0 + ob1;
        out[(size_t)(r0 + 3) * DIM + 32 + l] = v1 + ob1;
    }
}

// ---------------- launch ---------------------------------------------------
extern "C" void kernel_launch(void* const* d_in, const int* in_sizes, int n_in,
                              void* d_out, int out_size) {
    const float* x        = (const float*)d_in[0];
    const int*   edge_src = (const int*)d_in[2];
    const int*   edge_dst = (const int*)d_in[3];
    const int*   edge_ids = (const int*)d_in[4];
    const float* edge_w   = (const float*)d_in[5];
    const float* W0       = (const float*)d_in[6];
    const float* b0       = (const float*)d_in[7];
    const float* A1       = (const float*)d_in[8];
    const float* c1       = (const float*)d_in[9];
    const float* A2       = (const float*)d_in[10];
    const float* c2       = (const float*)d_in[11];
    const float* W_root   = (const float*)d_in[12];
    const float* b_conv   = (const float*)d_in[13];
    const float* W_ih     = (const float*)d_in[14];
    const float* W_hh     = (const float*)d_in[15];
    const float* b_ih     = (const float*)d_in[16];
    const float* b_hh     = (const float*)d_in[17];
    const float* W1       = (const float*)d_in[18];
    const float* b1       = (const float*)d_in[19];
    const float* W2       = (const float*)d_in[20];
    const float* b2       = (const float*)d_in[21];
    float* out = (float*)d_out;

    static const int MEGA_SMEM = MAXU * 2 * DIM * DIM * (int)sizeof(float); // 64 KB
    cudaFuncSetAttribute(k_mega, cudaFuncAttributeMaxDynamicSharedMemorySize, MEGA_SMEM);

    k_zero<<<(N_TGT + 255) / 256, 256>>>();
    k_prep<<<(DIM * G3 + 255) / 256, 256>>>(W0, W_ih, W_hh, W_root, W1, W2);
    k_setup<<<1, 128>>>(A1, c1);
    k_edgek<<<(E_NUM + 255) / 256, 256>>>(edge_ids, edge_w, edge_dst);
    k_slots<<<1, 128>>>();
    k_scan<<<1, 1024>>>();
    {
        dim3 g(512, 8, 1);
        k_tables<<<g, 256>>>(A1, c1, A2, c2);
    }
    k_csr<<<(E_NUM + 255) / 256, 256>>>(edge_src, edge_dst);
    k_h0<<<N_SRC / 32, 256>>>(x, b0);
    k_mega<<<(N_TGT / 4 * 32 + 255) / 256, 256, MEGA_SMEM>>>(b_conv, b_ih, b_hh, b1, b2, out);
}

// round 7
// speedup vs baseline: 1.3009x; 1.3009x over previous
#include <cuda_runtime.h>
#include <math.h>

#define N_SRC  80000
#define N_TGT  20000
#define E_NUM  80000
#define IN_DIM 128
#define DIM    64
#define EH     128
#define G3     192
#define NK     129   // up to 128 breakpoints -> 129 intervals
#define MAXU   2     // intervals cached in fast path (fallback covers the rest)

typedef unsigned long long ull;

// ---------------- f32x2 helpers ------------------------------------------
__device__ __forceinline__ ull pk2(float lo, float hi) {
    ull r; asm("mov.b64 %0, {%1,%2};" : "=l"(r) : "f"(lo), "f"(hi)); return r;
}
__device__ __forceinline__ void upk(ull v, float& lo, float& hi) {
    asm("mov.b64 {%0,%1}, %2;" : "=f"(lo), "=f"(hi) : "l"(v));
}
#define FMA_X2(d, a, b, c) asm("fma.rn.f32x2 %0, %1, %2, %3;" : "=l"(d) : "l"(a), "l"(b), "l"(c))

__device__ __forceinline__ float sigm(float x)  { return __fdividef(1.0f, 1.0f + __expf(-x)); }
__device__ __forceinline__ float tanhx(float x) { return 1.0f - __fdividef(2.0f, 1.0f + __expf(2.0f * x)); }

// ---------------- scratch (device globals; no allocation) ----------------
__device__ float g_h0[N_SRC * DIM];
__device__ float g_m[N_TGT * DIM];
__device__ float g_M[NK][DIM * DIM];
__device__ float g_P[NK][DIM * DIM];
__device__ float g_thr[EH];
__device__ unsigned char g_act[NK][EH];
__device__ int   g_kedge[E_NUM];
__device__ float g_aedge[E_NUM];
__device__ int   g_used[NK];
__device__ int   g_slotmap[NK];
__device__ int   g_slotk[MAXU];
__device__ int   g_usedlist[NK];
__device__ int   g_usedcnt;
__device__ int   g_nslots;
__device__ int   g_deg[N_TGT];
__device__ int   g_off[N_TGT];
__device__ int   g_cur[N_TGT];
__device__ unsigned g_cw[E_NUM];
__device__ float g_ca[E_NUM];
__device__ float g_W0t[IN_DIM * DIM];
__device__ ull   g_Wih_d[DIM * G3];
__device__ ull   g_Whh_d[DIM * G3];
__device__ ull   g_Wr_d[DIM * DIM];
__device__ ull   g_W1d[DIM * DIM];
__device__ ull   g_W2d[DIM * DIM];

// ---------------- zero scratch -------------------------------------------
__global__ void k_zero() {
    int idx = blockIdx.x * blockDim.x + threadIdx.x;
    if (idx < N_TGT) g_deg[idx] = 0;
    if (idx < NK)    g_used[idx] = 0;
}

// ---------------- weight prep: transpose + f32x2-dup tables --------------
__global__ void k_prep(const float* __restrict__ W0, const float* __restrict__ Wih,
                       const float* __restrict__ Whh, const float* __restrict__ Wr,
                       const float* __restrict__ W1, const float* __restrict__ W2) {
    int idx = blockIdx.x * blockDim.x + threadIdx.x;
    if (idx < IN_DIM * DIM) {            // W0t[i*64+o] = W0[o*128+i]
        int i = idx / DIM, o = idx % DIM;
        g_W0t[idx] = W0[o * IN_DIM + i];
    }
    if (idx < DIM * G3) {                // [o][g] dup tables
        int o = idx / G3, g = idx % G3;
        float wi = Wih[g * DIM + o]; g_Wih_d[idx] = pk2(wi, wi);
        float wh = Whh[g * DIM + o]; g_Whh_d[idx] = pk2(wh, wh);
    }
    if (idx < DIM * DIM) {
        int i = idx / DIM, o = idx % DIM;
        float wr = Wr[idx];          g_Wr_d[idx] = pk2(wr, wr);
        float w1 = W1[o * DIM + i];  g_W1d[idx] = pk2(w1, w1);
        float w2 = W2[o * DIM + i];  g_W2d[idx] = pk2(w2, w2);
    }
}

// ---------------- sort breakpoints, build active masks -------------------
__global__ void k_setup(const float* __restrict__ A1, const float* __restrict__ c1) {
    __shared__ float ts[EH], sorted[EH];
    int j = threadIdx.x;
    float s = A1[j];
    float c = c1[j];
    float t = (s != 0.0f) ? (-c / s) : 2.0e30f;
    ts[j] = t;
    __syncthreads();
    int rank = 0;
    for (int k = 0; k < EH; k++) {
        float tk = ts[k];
        rank += (tk < t) || (tk == t && k < j);
    }
    sorted[rank] = t;
    __syncthreads();
    g_thr[j] = sorted[j];
    const float BIGT = 1.0e29f;
    for (int k = 0; k < NK; k++) {
        float left  = (k > 0)  ? sorted[k - 1] : -2.0e30f;
        float right = (k < EH) ? sorted[k]     :  2.0e30f;
        bool linf = (left <= -BIGT), rinf = (right >= BIGT);
        float rep;
        if (linf && rinf)      rep = 0.0f;
        else if (linf)         rep = right - 1.0f;
        else if (rinf)         rep = left + 1.0f;
        else                   rep = 0.5f * (left + right);
        g_act[k][j] = (s * rep + c > 0.0f) ? 1 : 0;
    }
}

// ---------------- per-edge scalar + interval id + degree -----------------
__global__ void k_edgek(const int* __restrict__ eids, const float* __restrict__ ew,
                        const int* __restrict__ edst) {
    __shared__ float thr[EH];
    if (threadIdx.x < EH) thr[threadIdx.x] = g_thr[threadIdx.x];
    __syncthreads();
    int e = blockIdx.x * blockDim.x + threadIdx.x;
    if (e >= E_NUM) return;
    float a = ew[eids[e]];
    int k = 0;
#pragma unroll
    for (int j = 0; j < EH; j++) k += (thr[j] < a) ? 1 : 0;
    g_kedge[e] = k;
    g_aedge[e] = a;
    g_used[k]  = 1;
    atomicAdd(&g_deg[edst[e]], 1);
}

// ---------------- slot assignment + compact used list --------------------
__global__ void k_slots() {
    __shared__ int u[NK];
    for (int k = threadIdx.x; k < NK; k += 128) {
        u[k] = g_used[k];
        g_slotmap[k] = -1;
    }
    __syncthreads();
    if (threadIdx.x == 0) {
        int ns = 0;
        for (int k = 0; k < NK; k++) {
            if (u[k]) {
                if (ns < MAXU) { g_slotmap[k] = ns; g_slotk[ns] = k; }
                g_usedlist[ns] = k;
                ns++;
            }
        }
        g_usedcnt = ns;
        g_nslots = (ns < MAXU) ? ns : MAXU;
    }
}

// ---------------- exclusive scan of degrees -> CSR offsets ---------------
__global__ __launch_bounds__(1024) void k_scan() {
    __shared__ int wsum[32];
    int t = threadIdx.x;
    int start = t * 20;
    int s = 0;
#pragma unroll
    for (int i = 0; i < 20; i++) {
        int idx = start + i;
        if (idx < N_TGT) s += g_deg[idx];
    }
    int lane = t & 31, wid = t >> 5;
    int v = s;
#pragma unroll
    for (int off = 1; off < 32; off <<= 1) {
        int n = __shfl_up_sync(0xffffffffu, v, off);
        if (lane >= off) v += n;
    }
    if (lane == 31) wsum[wid] = v;
    __syncthreads();
    if (wid == 0) {
        int w = wsum[lane];
#pragma unroll
        for (int off = 1; off < 32; off <<= 1) {
            int n = __shfl_up_sync(0xffffffffu, w, off);
            if (lane >= off) w += n;
        }
        wsum[lane] = w;
    }
    __syncthreads();
    int excl = (v - s) + ((wid > 0) ? wsum[wid - 1] : 0);
    int run = excl;
#pragma unroll
    for (int i = 0; i < 20; i++) {
        int idx = start + i;
        if (idx < N_TGT) {
            g_off[idx] = run;
            g_cur[idx] = run;
            run += g_deg[idx];
        }
    }
}

// ---------------- build M_k / P_k only for used intervals ----------------
__global__ void k_tables(const float* __restrict__ A1, const float* __restrict__ c1,
                         const float* __restrict__ A2, const float* __restrict__ c2) {
    __shared__ float hs[EH], h2s[EH];
    int cnt = g_usedcnt;
    int t = threadIdx.x;
    for (int y = blockIdx.y; y < cnt; y += 8) {
        int k = g_usedlist[y];
        __syncthreads();
        if (t < EH) {
            float a = g_act[k][t] ? 1.0f : 0.0f;
            hs[t]  = A1[t] * a;
            h2s[t] = c1[t] * a;
        }
        __syncthreads();
        int w = t >> 5, l = t & 31;
        int io = blockIdx.x * 8 + w;
        const float4 av = *reinterpret_cast<const float4*>(A2 + (size_t)io * EH + l * 4);
        float m = av.x * hs[l * 4] + av.y * hs[l * 4 + 1] + av.z * hs[l * 4 + 2] + av.w * hs[l * 4 + 3];
        float p = av.x * h2s[l * 4] + av.y * h2s[l * 4 + 1] + av.z * h2s[l * 4 + 2] + av.w * h2s[l * 4 + 3];
#pragma unroll
        for (int off = 16; off > 0; off >>= 1) {
            m += __shfl_down_sync(0xffffffffu, m, off);
            p += __shfl_down_sync(0xffffffffu, p, off);
        }
        if (l == 0) {
            g_M[k][io] = m;
            g_P[k][io] = c2[io] + p;
        }
    }
}

// ---------------- CSR placement ------------------------------------------
__global__ void k_csr(const int* __restrict__ esrc, const int* __restrict__ edst) {
    int e = blockIdx.x * blockDim.x + threadIdx.x;
    if (e >= E_NUM) return;
    int dst = edst[e];
    int pos = atomicAdd(&g_cur[dst], 1);
    int k = g_kedge[e];
    int sm = g_slotmap[k];
    unsigned sc = (sm >= 0) ? (unsigned)sm : 7u;
    g_cw[pos] = (unsigned)esrc[e] | ((unsigned)k << 17) | (sc << 25);
    g_ca[pos] = g_aedge[e];
}

// ---------------- h0 = relu(x @ W0^T + b0), FFMA2 ------------------------
__global__ __launch_bounds__(256) void k_h0(const float* __restrict__ x,
                                            const float* __restrict__ b0) {
    int j  = threadIdx.x & 31;          // output pair index
    int gq = threadIdx.x >> 5;          // 0..7
    int row0 = blockIdx.x * 32 + gq * 4;
    ull acc[4] = {0ull, 0ull, 0ull, 0ull};
    const ull* __restrict__ W = reinterpret_cast<const ull*>(g_W0t);
#pragma unroll 4
    for (int ii = 0; ii < IN_DIM / 4; ii++) {
        float4 xv0 = *reinterpret_cast<const float4*>(x + (size_t)(row0 + 0) * IN_DIM + ii * 4);
        float4 xv1 = *reinterpret_cast<const float4*>(x + (size_t)(row0 + 1) * IN_DIM + ii * 4);
        float4 xv2 = *reinterpret_cast<const float4*>(x + (size_t)(row0 + 2) * IN_DIM + ii * 4);
        float4 xv3 = *reinterpret_cast<const float4*>(x + (size_t)(row0 + 3) * IN_DIM + ii * 4);
#define H0_STEP(comp, s)                                               \
        {                                                              \
            ull wv = W[(ii * 4 + s) * 32 + j];                         \
            FMA_X2(acc[0], pk2(xv0.comp, xv0.comp), wv, acc[0]);       \
            FMA_X2(acc[1], pk2(xv1.comp, xv1.comp), wv, acc[1]);       \
            FMA_X2(acc[2], pk2(xv2.comp, xv2.comp), wv, acc[2]);       \
            FMA_X2(acc[3], pk2(xv3.comp, xv3.comp), wv, acc[3]);       \
        }
        H0_STEP(x, 0) H0_STEP(y, 1) H0_STEP(z, 2) H0_STEP(w, 3)
#undef H0_STEP
    }
    float ba = b0[2 * j], bb = b0[2 * j + 1];
#pragma unroll
    for (int r = 0; r < 4; r++) {
        float lo, hi;
        upk(acc[r], lo, hi);
        float2 v;
        v.x = fmaxf(lo + ba, 0.0f);
        v.y = fmaxf(hi + bb, 0.0f);
        *reinterpret_cast<float2*>(g_h0 + (size_t)(row0 + r) * DIM + 2 * j) = v;
    }
}

// ---------------- gather + transform + conv: m = relu(agg/cnt + x@Wr + bc)
// warp per 2 targets; lean registers, no smem -> high occupancy.
__global__ __launch_bounds__(256) void k_gt(const float* __restrict__ b_conv) {
    int gw = (blockIdx.x * 256 + threadIdx.x) >> 5;
    int l  = threadIdx.x & 31;
    int t0 = gw * 2;
    if (t0 >= N_TGT) return;
    int ns = g_nslots;

    int offv[2], degv[2];
#pragma unroll
    for (int q = 0; q < 2; q++) { offv[q] = g_off[t0 + q]; degv[q] = g_deg[t0 + q]; }
    int dmax = max(degv[0], degv[1]);

    float S0a[MAXU][2], S0b[MAXU][2], S1a[MAXU][2], S1b[MAXU][2];
#pragma unroll
    for (int s = 0; s < MAXU; s++)
#pragma unroll
        for (int q = 0; q < 2; q++) { S0a[s][q] = 0; S0b[s][q] = 0; S1a[s][q] = 0; S1b[s][q] = 0; }
    float fbA[2] = {0, 0}, fbB[2] = {0, 0};

    for (int j = 0; j < dmax; j++) {
#pragma unroll
        for (int q = 0; q < 2; q++) {
            if (j < degv[q]) {                       // warp-uniform predicate
                int pos = offv[q] + j;
                unsigned w = __ldg(&g_cw[pos]);
                float a = __ldg(&g_ca[pos]);
                int src = (int)(w & 0x1FFFFu);
                unsigned sc = w >> 25;
                const float* __restrict__ hrow = g_h0 + (size_t)src * DIM;
                float xs0 = __ldg(hrow + l), xs1 = __ldg(hrow + 32 + l);
                float ax0 = a * xs0, ax1 = a * xs1;
#pragma unroll
                for (int s = 0; s < MAXU; s++) {
                    float sel = (sc == (unsigned)s) ? 1.0f : 0.0f;
                    S0a[s][q] += sel * xs0; S0b[s][q] += sel * xs1;
                    S1a[s][q] += sel * ax0; S1b[s][q] += sel * ax1;
                }
                if (sc == 7u) {                      // exact fallback (rare)
                    int k = (int)((w >> 17) & 0xFFu);
                    const float* __restrict__ M = g_M[k];
                    const float* __restrict__ P = g_P[k];
#pragma unroll 8
                    for (int i = 0; i < DIM; i++) {
                        float xi  = __shfl_sync(0xffffffffu, (i < 32) ? xs0 : xs1, i & 31);
                        float axi = a * xi;
                        fbA[q] += axi * M[i * DIM + l]      + xi * P[i * DIM + l];
                        fbB[q] += axi * M[i * DIM + 32 + l] + xi * P[i * DIM + 32 + l];
                    }
                }
            }
        }
    }

    // transform: acc = fallback + sum_s S1_s@M_s + S0_s@P_s  (pairs = targets)
    ull accA = pk2(fbA[0], fbA[1]);
    ull accB = pk2(fbB[0], fbB[1]);
#pragma unroll
    for (int s = 0; s < MAXU; s++) {
        if (s >= ns) break;
        const float* __restrict__ Mk = g_M[g_slotk[s]];
        const float* __restrict__ Pk = g_P[g_slotk[s]];
#pragma unroll 4
        for (int i = 0; i < DIM; i++) {
            float m0 = __ldg(Mk + i * DIM + l), m1 = __ldg(Mk + i * DIM + 32 + l);
            float p0 = __ldg(Pk + i * DIM + l), p1 = __ldg(Pk + i * DIM + 32 + l);
            float t1q0 = __shfl_sync(0xffffffffu, (i < 32) ? S1a[s][0] : S1b[s][0], i & 31);
            float t1q1 = __shfl_sync(0xffffffffu, (i < 32) ? S1a[s][1] : S1b[s][1], i & 31);
            float t0q0 = __shfl_sync(0xffffffffu, (i < 32) ? S0a[s][0] : S0b[s][0], i & 31);
            float t0q1 = __shfl_sync(0xffffffffu, (i < 32) ? S0a[s][1] : S0b[s][1], i & 31);
            ull s1p = pk2(t1q0, t1q1), s0p = pk2(t0q0, t0q1);
            FMA_X2(accA, s1p, pk2(m0, m0), accA); FMA_X2(accA, s0p, pk2(p0, p0), accA);
            FMA_X2(accB, s1p, pk2(m1, m1), accB); FMA_X2(accB, s0p, pk2(p1, p1), accB);
        }
    }

    // conv: m = relu(acc/deg + x_tgt@W_root + b_conv)
    float xt0[2], xt1[2];
#pragma unroll
    for (int q = 0; q < 2; q++) {
        xt0[q] = g_h0[(size_t)(t0 + q) * DIM + l];
        xt1[q] = g_h0[(size_t)(t0 + q) * DIM + 32 + l];
    }
    {
        float inv0 = __fdividef(1.0f, fmaxf((float)degv[0], 1.0f));
        float inv1 = __fdividef(1.0f, fmaxf((float)degv[1], 1.0f));
        float v0, v1;
        upk(accA, v0, v1); accA = pk2(v0 * inv0, v1 * inv1);
        upk(accB, v0, v1); accB = pk2(v0 * inv0, v1 * inv1);
    }
#pragma unroll 4
    for (int i = 0; i < DIM; i++) {
        ull wv0 = g_Wr_d[i * DIM + l];
        ull wv1 = g_Wr_d[i * DIM + 32 + l];
        float x0 = __shfl_sync(0xffffffffu, (i < 32) ? xt0[0] : xt1[0], i & 31);
        float x1 = __shfl_sync(0xffffffffu, (i < 32) ? xt0[1] : xt1[1], i & 31);
        ull xp = pk2(x0, x1);
        FMA_X2(accA, xp, wv0, accA);
        FMA_X2(accB, xp, wv1, accB);
    }
    {
        float bc0 = b_conv[l], bc1 = b_conv[32 + l];
        float v0, v1;
        upk(accA, v0, v1);
        g_m[(size_t)(t0 + 0) * DIM + l] = fmaxf(v0 + bc0, 0.0f);
        g_m[(size_t)(t0 + 1) * DIM + l] = fmaxf(v1 + bc0, 0.0f);
        upk(accB, v0, v1);
        g_m[(size_t)(t0 + 0) * DIM + 32 + l] = fmaxf(v0 + bc1, 0.0f);
        g_m[(size_t)(t0 + 1) * DIM + 32 + l] = fmaxf(v1 + bc1, 0.0f);
    }
}

// ---------------- gi (in regs) + GRU x3 + head ---------------------------
// warp per 4 targets.
__global__ __launch_bounds__(256) void k_grufull(const float* __restrict__ b_ih,
                                                 const float* __restrict__ b_hh,
                                                 const float* __restrict__ b1,
                                                 const float* __restrict__ b2,
                                                 float* __restrict__ out) {
    int gw = (blockIdx.x * 256 + threadIdx.x) >> 5;
    int l = threadIdx.x & 31;
    int r0 = gw * 4;
    if (r0 >= N_TGT) return;

    float m0[4], m1[4], xt0[4], xt1[4];
#pragma unroll
    for (int q = 0; q < 4; q++) {
        m0[q]  = g_m[(size_t)(r0 + q) * DIM + l];
        m1[q]  = g_m[(size_t)(r0 + q) * DIM + 32 + l];
        xt0[q] = g_h0[(size_t)(r0 + q) * DIM + l];
        xt1[q] = g_h0[(size_t)(r0 + q) * DIM + 32 + l];
    }

    // gi = m @ W_ih^T + b_ih (registers only)
    ull gip[6][2];
#pragma unroll
    for (int t = 0; t < 6; t++) { gip[t][0] = 0ull; gip[t][1] = 0ull; }
#pragma unroll 2
    for (int o = 0; o < DIM; o++) {
        float mq[4];
#pragma unroll
        for (int q = 0; q < 4; q++)
            mq[q] = __shfl_sync(0xffffffffu, (o < 32) ? m0[q] : m1[q], o & 31);
        ull mp01 = pk2(mq[0], mq[1]), mp23 = pk2(mq[2], mq[3]);
#pragma unroll
        for (int t = 0; t < 6; t++) {
            ull wv = g_Wih_d[o * G3 + l + 32 * t];
            FMA_X2(gip[t][0], mp01, wv, gip[t][0]);
            FMA_X2(gip[t][1], mp23, wv, gip[t][1]);
        }
    }
    float gi[6][4];
#pragma unroll
    for (int t = 0; t < 6; t++) {
        float bi = b_ih[l + 32 * t];
        float v0, v1;
        upk(gip[t][0], v0, v1); gi[t][0] = v0 + bi; gi[t][1] = v1 + bi;
        upk(gip[t][1], v0, v1); gi[t][2] = v0 + bi; gi[t][3] = v1 + bi;
    }

    // GRU x3 (h init = x_tgt)
    float h0r[4], h1r[4];
#pragma unroll
    for (int q = 0; q < 4; q++) { h0r[q] = xt0[q]; h1r[q] = xt1[q]; }
    float bh[6];
#pragma unroll
    for (int t = 0; t < 6; t++) bh[t] = b_hh[l + 32 * t];

    for (int step = 0; step < 3; step++) {
        ull ghp[6][2];
#pragma unroll
        for (int t = 0; t < 6; t++) {
            ghp[t][0] = pk2(bh[t], bh[t]);
            ghp[t][1] = ghp[t][0];
        }
#pragma unroll 2
        for (int i = 0; i < DIM; i++) {
            float hq[4];
#pragma unroll
            for (int q = 0; q < 4; q++)
                hq[q] = __shfl_sync(0xffffffffu, (i < 32) ? h0r[q] : h1r[q], i & 31);
            ull hp01 = pk2(hq[0], hq[1]), hp23 = pk2(hq[2], hq[3]);
#pragma unroll
            for (int t = 0; t < 6; t++) {
                ull wv = g_Whh_d[i * G3 + l + 32 * t];
                FMA_X2(ghp[t][0], hp01, wv, ghp[t][0]);
                FMA_X2(ghp[t][1], hp23, wv, ghp[t][1]);
            }
        }
#pragma unroll
        for (int q = 0; q < 4; q++) {
            float ghv[6];
#pragma unroll
            for (int t = 0; t < 6; t++) {
                float lo, hi;
                upk(ghp[t][q >> 1], lo, hi);
                ghv[t] = (q & 1) ? hi : lo;
            }
            float rr0 = sigm(gi[0][q] + ghv[0]);
            float rr1 = sigm(gi[1][q] + ghv[1]);
            float zz0 = sigm(gi[2][q] + ghv[2]);
            float zz1 = sigm(gi[3][q] + ghv[3]);
            float nn0 = tanhx(gi[4][q] + rr0 * ghv[4]);
            float nn1 = tanhx(gi[5][q] + rr1 * ghv[5]);
            h0r[q] = (1.0f - zz0) * nn0 + zz0 * h0r[q];
            h1r[q] = (1.0f - zz1) * nn1 + zz1 * h1r[q];
        }
    }

    // head: a = relu(h @ W1^T + b1); out = a @ W2^T + b2
    ull aA01 = 0ull, aA23 = 0ull, aB01 = 0ull, aB23 = 0ull;
#pragma unroll 4
    for (int i = 0; i < DIM; i++) {
        float hq[4];
#pragma unroll
        for (int q = 0; q < 4; q++)
            hq[q] = __shfl_sync(0xffffffffu, (i < 32) ? h0r[q] : h1r[q], i & 31);
        ull hp01 = pk2(hq[0], hq[1]), hp23 = pk2(hq[2], hq[3]);
        ull wv0 = g_W1d[i * DIM + l], wv1 = g_W1d[i * DIM + 32 + l];
        FMA_X2(aA01, hp01, wv0, aA01); FMA_X2(aA23, hp23, wv0, aA23);
        FMA_X2(aB01, hp01, wv1, aB01); FMA_X2(aB23, hp23, wv1, aB23);
    }
    float a0[4], a1[4];
    {
        float bb0 = b1[l], bb1 = b1[32 + l];
        float v0, v1;
        upk(aA01, v0, v1); a0[0] = fmaxf(v0 + bb0, 0.0f); a0[1] = fmaxf(v1 + bb0, 0.0f);
        upk(aA23, v0, v1); a0[2] = fmaxf(v0 + bb0, 0.0f); a0[3] = fmaxf(v1 + bb0, 0.0f);
        upk(aB01, v0, v1); a1[0] = fmaxf(v0 + bb1, 0.0f); a1[1] = fmaxf(v1 + bb1, 0.0f);
        upk(aB23, v0, v1); a1[2] = fmaxf(v0 + bb1, 0.0f); a1[3] = fmaxf(v1 + bb1, 0.0f);
    }
    ull cA01 = 0ull, cA23 = 0ull, cB01 = 0ull, cB23 = 0ull;
#pragma unroll 4
    for (int i = 0; i < DIM; i++) {
        float aq[4];
#pragma unroll
        for (int q = 0; q < 4; q++)
            aq[q] = __shfl_sync(0xffffffffu, (i < 32) ? a0[q] : a1[q], i & 31);
        ull ap01 = pk2(aq[0], aq[1]), ap23 = pk2(aq[2], aq[3]);
        ull wv0 = g_W2d[i * DIM + l], wv1 = g_W2d[i * DIM + 32 + l];
        FMA_X2(cA01, ap01, wv0, cA01); FMA_X2(cA23, ap23, wv0, cA23);
        FMA_X2(cB01, ap01, wv1, cB01); FMA_X2(cB23, ap23, wv1, cB23);
    }
    {
        float ob0 = b2[l], ob1 = b2[32 + l];
        float v0, v1;
        upk(cA01, v0, v1);
        out[(size_t)(r0 + 0) * DIM + l] = v0 + ob0;
        out[(size_t)(r0 + 1) * DIM + l] = v1 + ob0;
        upk(cA23, v0, v1);
        out[(size_t)(r0 + 2) * DIM + l] = v0 + ob0;
        out[(size_t)(r0 + 3) * DIM + l] = v1 + ob0;
        upk(cB01, v0, v1);
        out[(size_t)(r0 + 0) * DIM + 32 + l] = v0 + ob1;
        out[(size_t)(r0 + 1) * DIM + 32 + l] = v1 + ob1;
        upk(cB23, v0, v1);
        out[(size_t)(r0 + 2) * DIM + 32 + l] = v0 + ob1;
        out[(size_t)(r0 + 3) * DIM + 32 + l] = v1 + ob1;
    }
}

// ---------------- launch ---------------------------------------------------
extern "C" void kernel_launch(void* const* d_in, const int* in_sizes, int n_in,
                              void* d_out, int out_size) {
    const float* x        = (const float*)d_in[0];
    const int*   edge_src = (const int*)d_in[2];
    const int*   edge_dst = (const int*)d_in[3];
    const int*   edge_ids = (const int*)d_in[4];
    const float* edge_w   = (const float*)d_in[5];
    const float* W0       = (const float*)d_in[6];
    const float* b0       = (const float*)d_in[7];
    const float* A1       = (const float*)d_in[8];
    const float* c1       = (const float*)d_in[9];
    const float* A2       = (const float*)d_in[10];
    const float* c2       = (const float*)d_in[11];
    const float* W_root   = (const float*)d_in[12];
    const float* b_conv   = (const float*)d_in[13];
    const float* W_ih     = (const float*)d_in[14];
    const float* W_hh     = (const float*)d_in[15];
    const float* b_ih     = (const float*)d_in[16];
    const float* b_hh     = (const float*)d_in[17];
    const float* W1       = (const float*)d_in[18];
    const float* b1       = (const float*)d_in[19];
    const float* W2       = (const float*)d_in[20];
    const float* b2       = (const float*)d_in[21];
    float* out = (float*)d_out;

    k_zero<<<(N_TGT + 255) / 256, 256>>>();
    k_prep<<<(DIM * G3 + 255) / 256, 256>>>(W0, W_ih, W_hh, W_root, W1, W2);
    k_setup<<<1, 128>>>(A1, c1);
    k_edgek<<<(E_NUM + 255) / 256, 256>>>(edge_ids, edge_w, edge_dst);
    k_slots<<<1, 128>>>();
    k_scan<<<1, 1024>>>();
    {
        dim3 g(512, 8, 1);
        k_tables<<<g, 256>>>(A1, c1, A2, c2);
    }
    k_csr<<<(E_NUM + 255) / 256, 256>>>(edge_src, edge_dst);
    k_h0<<<N_SRC / 32, 256>>>(x, b0);
    k_gt<<<(N_TGT / 2 * 32 + 255) / 256, 256>>>(b_conv);
    k_grufull<<<(N_TGT / 4 * 32 + 255) / 256, 256>>>(b_ih, b_hh, b1, b2, out);
}

// round 8
// speedup vs baseline: 1.4444x; 1.1104x over previous
#include <cuda_runtime.h>
#include <math.h>

#define N_SRC  80000
#define N_TGT  20000
#define E_NUM  80000
#define IN_DIM 128
#define DIM    64
#define EH     128
#define G3     192
#define NK     129
#define MAXU   2

typedef unsigned long long ull;

__device__ __forceinline__ ull pk2(float lo, float hi) {
    ull r; asm("mov.b64 %0, {%1,%2};" : "=l"(r) : "f"(lo), "f"(hi)); return r;
}
__device__ __forceinline__ void upk(ull v, float& lo, float& hi) {
    asm("mov.b64 {%0,%1}, %2;" : "=f"(lo), "=f"(hi) : "l"(v));
}
#define FMA_X2(d, a, b, c) asm("fma.rn.f32x2 %0, %1, %2, %3;" : "=l"(d) : "l"(a), "l"(b), "l"(c))

__device__ __forceinline__ float sigm(float x)  { return __fdividef(1.0f, 1.0f + __expf(-x)); }
__device__ __forceinline__ float tanhx(float x) { return 1.0f - __fdividef(2.0f, 1.0f + __expf(2.0f * x)); }

// ---------------- scratch ------------------------------------------------
__device__ float g_h0[N_SRC * DIM];
__device__ float g_m[N_TGT * DIM];
__device__ float g_M[NK][DIM * DIM];
__device__ float g_P[NK][DIM * DIM];
__device__ float g_T[NK][DIM * 128];     // packed: [i][lane] = {M_lo,M_hi,P_lo,P_hi}
__device__ float g_thr[EH];
__device__ unsigned char g_act[NK][EH];
__device__ int   g_kedge[E_NUM];
__device__ float g_aedge[E_NUM];
__device__ int   g_used[NK];
__device__ int   g_slotmap[NK];
__device__ int   g_slotk[MAXU];
__device__ int   g_usedlist[NK];
__device__ int   g_usedcnt;
__device__ int   g_nslots;
__device__ int   g_deg[N_TGT];
__device__ int   g_off[N_TGT];
__device__ int   g_cur[N_TGT];
__device__ unsigned g_cw[E_NUM];
__device__ float g_ca[E_NUM];
__device__ float g_W0t[IN_DIM * DIM];
__device__ ull   g_Wih_d[DIM * G3];
__device__ ull   g_Whh_d[DIM * G3];
__device__ ull   g_Wr_d[DIM * DIM];
__device__ ull   g_W1d[DIM * DIM];
__device__ ull   g_W2d[DIM * DIM];

// ================= kA: zero + prep + setup (merged) ======================
__global__ __launch_bounds__(256) void kA(const float* __restrict__ W0,
                                          const float* __restrict__ Wih,
                                          const float* __restrict__ Whh,
                                          const float* __restrict__ Wr,
                                          const float* __restrict__ W1,
                                          const float* __restrict__ W2,
                                          const float* __restrict__ A1,
                                          const float* __restrict__ c1) {
    int b = blockIdx.x;
    int t = threadIdx.x;
    if (b < 79) {                               // zero
        int idx = b * 256 + t;
        if (idx < N_TGT) g_deg[idx] = 0;
        if (idx < NK)    g_used[idx] = 0;
        return;
    }
    if (b < 127) {                              // prep
        int idx = (b - 79) * 256 + t;
        if (idx < IN_DIM * DIM) {
            int i = idx / DIM, o = idx % DIM;
            g_W0t[idx] = W0[o * IN_DIM + i];
        }
        if (idx < DIM * G3) {
            int o = idx / G3, g = idx % G3;
            float wi = Wih[g * DIM + o]; g_Wih_d[idx] = pk2(wi, wi);
            float wh = Whh[g * DIM + o]; g_Whh_d[idx] = pk2(wh, wh);
        }
        if (idx < DIM * DIM) {
            int i = idx / DIM, o = idx % DIM;
            float wr = Wr[idx];          g_Wr_d[idx] = pk2(wr, wr);
            float w1 = W1[o * DIM + i];  g_W1d[idx] = pk2(w1, w1);
            float w2 = W2[o * DIM + i];  g_W2d[idx] = pk2(w2, w2);
        }
        return;
    }
    // setup (1 block, threads < 128)
    __shared__ float ts[EH], sorted[EH];
    if (t >= EH) return;
    int j = t;
    float s = A1[j];
    float c = c1[j];
    float th = (s != 0.0f) ? (-c / s) : 2.0e30f;
    ts[j] = th;
    __syncwarp();
    __syncthreads();
    int rank = 0;
    for (int k = 0; k < EH; k++) {
        float tk = ts[k];
        rank += (tk < th) || (tk == th && k < j);
    }
    sorted[rank] = th;
    __syncthreads();
    g_thr[j] = sorted[j];
    const float BIGT = 1.0e29f;
    for (int k = 0; k < NK; k++) {
        float left  = (k > 0)  ? sorted[k - 1] : -2.0e30f;
        float right = (k < EH) ? sorted[k]     :  2.0e30f;
        bool linf = (left <= -BIGT), rinf = (right >= BIGT);
        float rep;
        if (linf && rinf)      rep = 0.0f;
        else if (linf)         rep = right - 1.0f;
        else if (rinf)         rep = left + 1.0f;
        else                   rep = 0.5f * (left + right);
        g_act[k][j] = (s * rep + c > 0.0f) ? 1 : 0;
    }
}

// ================= kB: h0 + edgek (merged) ===============================
#define H0_BLOCKS (N_SRC / 32)   // 2500
__global__ __launch_bounds__(256) void kB(const float* __restrict__ x,
                                          const float* __restrict__ b0,
                                          const int* __restrict__ eids,
                                          const float* __restrict__ ew,
                                          const int* __restrict__ edst) {
    __shared__ float sthr[EH];
    if (blockIdx.x < H0_BLOCKS) {
        // ---- h0 = relu(x @ W0^T + b0) ----
        int j  = threadIdx.x & 31;
        int gq = threadIdx.x >> 5;
        int row0 = blockIdx.x * 32 + gq * 4;
        ull acc[4] = {0ull, 0ull, 0ull, 0ull};
        const ull* __restrict__ W = reinterpret_cast<const ull*>(g_W0t);
#pragma unroll 4
        for (int ii = 0; ii < IN_DIM / 4; ii++) {
            float4 xv0 = *reinterpret_cast<const float4*>(x + (size_t)(row0 + 0) * IN_DIM + ii * 4);
            float4 xv1 = *reinterpret_cast<const float4*>(x + (size_t)(row0 + 1) * IN_DIM + ii * 4);
            float4 xv2 = *reinterpret_cast<const float4*>(x + (size_t)(row0 + 2) * IN_DIM + ii * 4);
            float4 xv3 = *reinterpret_cast<const float4*>(x + (size_t)(row0 + 3) * IN_DIM + ii * 4);
#define H0_STEP(comp, s)                                               \
            {                                                          \
                ull wv = W[(ii * 4 + s) * 32 + j];                     \
                FMA_X2(acc[0], pk2(xv0.comp, xv0.comp), wv, acc[0]);   \
                FMA_X2(acc[1], pk2(xv1.comp, xv1.comp), wv, acc[1]);   \
                FMA_X2(acc[2], pk2(xv2.comp, xv2.comp), wv, acc[2]);   \
                FMA_X2(acc[3], pk2(xv3.comp, xv3.comp), wv, acc[3]);   \
            }
            H0_STEP(x, 0) H0_STEP(y, 1) H0_STEP(z, 2) H0_STEP(w, 3)
#undef H0_STEP
        }
        float ba = b0[2 * j], bb = b0[2 * j + 1];
#pragma unroll
        for (int r = 0; r < 4; r++) {
            float lo, hi;
            upk(acc[r], lo, hi);
            float2 v;
            v.x = fmaxf(lo + ba, 0.0f);
            v.y = fmaxf(hi + bb, 0.0f);
            *reinterpret_cast<float2*>(g_h0 + (size_t)(row0 + r) * DIM + 2 * j) = v;
        }
    } else {
        // ---- edgek ----
        if (threadIdx.x < EH) sthr[threadIdx.x] = g_thr[threadIdx.x];
        __syncthreads();
        int e = (blockIdx.x - H0_BLOCKS) * 256 + threadIdx.x;
        if (e >= E_NUM) return;
        float a = ew[eids[e]];
        int k = 0;
#pragma unroll
        for (int j = 0; j < EH; j++) k += (sthr[j] < a) ? 1 : 0;
        g_kedge[e] = k;
        g_aedge[e] = a;
        g_used[k]  = 1;
        atomicAdd(&g_deg[edst[e]], 1);
    }
}

// ================= kC: scan (block 0) + slots (block 1) ==================
__global__ __launch_bounds__(1024) void kC() {
    if (blockIdx.x == 0) {
        __shared__ int wsum[32];
        int t = threadIdx.x;
        int start = t * 20;
        int s = 0;
#pragma unroll
        for (int i = 0; i < 20; i++) {
            int idx = start + i;
            if (idx < N_TGT) s += g_deg[idx];
        }
        int lane = t & 31, wid = t >> 5;
        int v = s;
#pragma unroll
        for (int off = 1; off < 32; off <<= 1) {
            int n = __shfl_up_sync(0xffffffffu, v, off);
            if (lane >= off) v += n;
        }
        if (lane == 31) wsum[wid] = v;
        __syncthreads();
        if (wid == 0) {
            int w = wsum[lane];
#pragma unroll
            for (int off = 1; off < 32; off <<= 1) {
                int n = __shfl_up_sync(0xffffffffu, w, off);
                if (lane >= off) w += n;
            }
            wsum[lane] = w;
        }
        __syncthreads();
        int excl = (v - s) + ((wid > 0) ? wsum[wid - 1] : 0);
        int run = excl;
#pragma unroll
        for (int i = 0; i < 20; i++) {
            int idx = start + i;
            if (idx < N_TGT) {
                g_off[idx] = run;
                g_cur[idx] = run;
                run += g_deg[idx];
            }
        }
    } else {
        if (threadIdx.x == 0) {
            int ns = 0;
            for (int k = 0; k < NK; k++) {
                g_slotmap[k] = -1;
                if (g_used[k]) {
                    if (ns < MAXU) { g_slotmap[k] = ns; g_slotk[ns] = k; }
                    g_usedlist[ns] = k;
                    ns++;
                }
            }
            g_usedcnt = ns;
            g_nslots = (ns < MAXU) ? ns : MAXU;
        }
    }
}

// ================= kD: csr + tables (merged) =============================
#define CSR_BLOCKS 313
__global__ __launch_bounds__(256) void kD(const int* __restrict__ esrc,
                                          const int* __restrict__ edst,
                                          const float* __restrict__ A1,
                                          const float* __restrict__ c1,
                                          const float* __restrict__ A2,
                                          const float* __restrict__ c2) {
    __shared__ float hs[EH], h2s[EH];
    if (blockIdx.x < CSR_BLOCKS) {
        int e = blockIdx.x * 256 + threadIdx.x;
        if (e >= E_NUM) return;
        int dst = edst[e];
        int pos = atomicAdd(&g_cur[dst], 1);
        int k = g_kedge[e];
        int sm = g_slotmap[k];
        unsigned sc = (sm >= 0) ? (unsigned)sm : 7u;
        g_cw[pos] = (unsigned)esrc[e] | ((unsigned)k << 17) | (sc << 25);
        g_ca[pos] = g_aedge[e];
    } else {
        int bb = blockIdx.x - CSR_BLOCKS;      // 0..4095
        int bx = bb & 511;
        int by = bb >> 9;                      // 0..7
        int cnt = g_usedcnt;
        int t = threadIdx.x;
        for (int y = by; y < cnt; y += 8) {
            int k = g_usedlist[y];
            __syncthreads();
            if (t < EH) {
                float a = g_act[k][t] ? 1.0f : 0.0f;
                hs[t]  = A1[t] * a;
                h2s[t] = c1[t] * a;
            }
            __syncthreads();
            int w = t >> 5, l = t & 31;
            int io = bx * 8 + w;
            const float4 av = *reinterpret_cast<const float4*>(A2 + (size_t)io * EH + l * 4);
            float m = av.x * hs[l * 4] + av.y * hs[l * 4 + 1] + av.z * hs[l * 4 + 2] + av.w * hs[l * 4 + 3];
            float p = av.x * h2s[l * 4] + av.y * h2s[l * 4 + 1] + av.z * h2s[l * 4 + 2] + av.w * h2s[l * 4 + 3];
#pragma unroll
            for (int off = 16; off > 0; off >>= 1) {
                m += __shfl_down_sync(0xffffffffu, m, off);
                p += __shfl_down_sync(0xffffffffu, p, off);
            }
            if (l == 0) {
                float pv = c2[io] + p;
                g_M[k][io] = m;
                g_P[k][io] = pv;
                int i = io >> 6, o = io & 63;
                int tb = (i * 32 + (o & 31)) * 4 + ((o >> 5) & 1);
                g_T[k][tb]     = m;     // M at +0/+1
                g_T[k][tb + 2] = pv;    // P at +2/+3
            }
        }
    }
}

// ================= k_gt: gather + transform + conv -> m ==================
// warp per 4 targets; smem staging for S and xt broadcasts.
__global__ __launch_bounds__(256) void k_gt(const float* __restrict__ b_conv) {
    __shared__ float st[8][64 * 16];           // per-warp staging (4 KB each)
    int wid = threadIdx.x >> 5;
    int l   = threadIdx.x & 31;
    int gw  = (blockIdx.x * 256 + threadIdx.x) >> 5;
    int t0  = gw * 4;
    float* sw = st[wid];
    int ns = g_nslots;

    int offv[4], degv[4];
#pragma unroll
    for (int q = 0; q < 4; q++) { offv[q] = g_off[t0 + q]; degv[q] = g_deg[t0 + q]; }
    int dmax = max(max(degv[0], degv[1]), max(degv[2], degv[3]));

    float S1a[MAXU][4], S0a[MAXU][4], S1b[MAXU][4], S0b[MAXU][4];
#pragma unroll
    for (int s = 0; s < MAXU; s++)
#pragma unroll
        for (int q = 0; q < 4; q++) { S1a[s][q] = 0; S0a[s][q] = 0; S1b[s][q] = 0; S0b[s][q] = 0; }
    float fbA[4] = {0, 0, 0, 0}, fbB[4] = {0, 0, 0, 0};

    // ---- gather with one-ahead meta prefetch ----
    unsigned wv[4]; float av[4];
#pragma unroll
    for (int q = 0; q < 4; q++)
        if (degv[q] > 0) { wv[q] = __ldg(&g_cw[offv[q]]); av[q] = __ldg(&g_ca[offv[q]]); }
    for (int j = 0; j < dmax; j++) {
        unsigned wn[4]; float an[4];
#pragma unroll
        for (int q = 0; q < 4; q++)
            if (j + 1 < degv[q]) { wn[q] = __ldg(&g_cw[offv[q] + j + 1]); an[q] = __ldg(&g_ca[offv[q] + j + 1]); }
#pragma unroll
        for (int q = 0; q < 4; q++) {
            if (j < degv[q]) {
                unsigned w = wv[q];
                float a = av[q];
                int src = (int)(w & 0x1FFFFu);
                unsigned sc = w >> 25;
                const float* __restrict__ hrow = g_h0 + (size_t)src * DIM;
                float xs0 = __ldg(hrow + l), xs1 = __ldg(hrow + 32 + l);
                float ax0 = a * xs0, ax1 = a * xs1;
#pragma unroll
                for (int s = 0; s < MAXU; s++) {
                    float sel = (sc == (unsigned)s) ? 1.0f : 0.0f;
                    S1a[s][q] += sel * ax0; S1b[s][q] += sel * ax1;
                    S0a[s][q] += sel * xs0; S0b[s][q] += sel * xs1;
                }
                if (sc == 7u) {
                    int k = (int)((w >> 17) & 0xFFu);
                    const float* __restrict__ M = g_M[k];
                    const float* __restrict__ P = g_P[k];
#pragma unroll 8
                    for (int i = 0; i < DIM; i++) {
                        float xi  = __shfl_sync(0xffffffffu, (i < 32) ? xs0 : xs1, i & 31);
                        float axi = a * xi;
                        fbA[q] += axi * M[i * DIM + l]      + xi * P[i * DIM + l];
                        fbB[q] += axi * M[i * DIM + 32 + l] + xi * P[i * DIM + 32 + l];
                    }
                }
            }
        }
#pragma unroll
        for (int q = 0; q < 4; q++) { wv[q] = wn[q]; av[q] = an[q]; }
    }

    // ---- stage S into smem: [i][s*8 + {S1:0..3, S0:4..7}] ----
#pragma unroll
    for (int s = 0; s < MAXU; s++) {
        *reinterpret_cast<float4*>(sw + l * 16 + s * 8)            = make_float4(S1a[s][0], S1a[s][1], S1a[s][2], S1a[s][3]);
        *reinterpret_cast<float4*>(sw + l * 16 + s * 8 + 4)        = make_float4(S0a[s][0], S0a[s][1], S0a[s][2], S0a[s][3]);
        *reinterpret_cast<float4*>(sw + (32 + l) * 16 + s * 8)     = make_float4(S1b[s][0], S1b[s][1], S1b[s][2], S1b[s][3]);
        *reinterpret_cast<float4*>(sw + (32 + l) * 16 + s * 8 + 4) = make_float4(S0b[s][0], S0b[s][1], S0b[s][2], S0b[s][3]);
    }
    __syncwarp();

    // ---- transform ----
    ull accA[2], accB[2];
    accA[0] = pk2(fbA[0], fbA[1]); accA[1] = pk2(fbA[2], fbA[3]);
    accB[0] = pk2(fbB[0], fbB[1]); accB[1] = pk2(fbB[2], fbB[3]);
#pragma unroll
    for (int s = 0; s < MAXU; s++) {
        if (s >= ns) break;
        const float4* __restrict__ Tk = reinterpret_cast<const float4*>(g_T[g_slotk[s]]);
#pragma unroll 4
        for (int i = 0; i < DIM; i++) {
            float4 sv1 = *reinterpret_cast<const float4*>(sw + i * 16 + s * 8);
            float4 sv0 = *reinterpret_cast<const float4*>(sw + i * 16 + s * 8 + 4);
            float4 tv  = __ldg(&Tk[i * 32 + l]);   // {M_lo, M_hi, P_lo, P_hi}
            ull s1p01 = pk2(sv1.x, sv1.y), s1p23 = pk2(sv1.z, sv1.w);
            ull s0p01 = pk2(sv0.x, sv0.y), s0p23 = pk2(sv0.z, sv0.w);
            FMA_X2(accA[0], s1p01, pk2(tv.x, tv.x), accA[0]);
            FMA_X2(accA[1], s1p23, pk2(tv.x, tv.x), accA[1]);
            FMA_X2(accA[0], s0p01, pk2(tv.z, tv.z), accA[0]);
            FMA_X2(accA[1], s0p23, pk2(tv.z, tv.z), accA[1]);
            FMA_X2(accB[0], s1p01, pk2(tv.y, tv.y), accB[0]);
            FMA_X2(accB[1], s1p23, pk2(tv.y, tv.y), accB[1]);
            FMA_X2(accB[0], s0p01, pk2(tv.w, tv.w), accB[0]);
            FMA_X2(accB[1], s0p23, pk2(tv.w, tv.w), accB[1]);
        }
    }

    // ---- divide by counts ----
    {
        float i0 = __fdividef(1.0f, fmaxf((float)degv[0], 1.0f));
        float i1 = __fdividef(1.0f, fmaxf((float)degv[1], 1.0f));
        float i2 = __fdividef(1.0f, fmaxf((float)degv[2], 1.0f));
        float i3 = __fdividef(1.0f, fmaxf((float)degv[3], 1.0f));
        float v0, v1;
        upk(accA[0], v0, v1); accA[0] = pk2(v0 * i0, v1 * i1);
        upk(accA[1], v0, v1); accA[1] = pk2(v0 * i2, v1 * i3);
        upk(accB[0], v0, v1); accB[0] = pk2(v0 * i0, v1 * i1);
        upk(accB[1], v0, v1); accB[1] = pk2(v0 * i2, v1 * i3);
    }

    // ---- stage x_tgt + conv root matvec ----
    float xt0[4], xt1[4];
#pragma unroll
    for (int q = 0; q < 4; q++) {
        xt0[q] = g_h0[(size_t)(t0 + q) * DIM + l];
        xt1[q] = g_h0[(size_t)(t0 + q) * DIM + 32 + l];
    }
    __syncwarp();
    *reinterpret_cast<float4*>(sw + l * 4)        = make_float4(xt0[0], xt0[1], xt0[2], xt0[3]);
    *reinterpret_cast<float4*>(sw + (32 + l) * 4) = make_float4(xt1[0], xt1[1], xt1[2], xt1[3]);
    __syncwarp();
#pragma unroll 4
    for (int i = 0; i < DIM; i++) {
        float4 xv = *reinterpret_cast<const float4*>(sw + i * 4);
        ull wv0 = g_Wr_d[i * DIM + l];
        ull wv1 = g_Wr_d[i * DIM + 32 + l];
        ull xp01 = pk2(xv.x, xv.y), xp23 = pk2(xv.z, xv.w);
        FMA_X2(accA[0], xp01, wv0, accA[0]); FMA_X2(accA[1], xp23, wv0, accA[1]);
        FMA_X2(accB[0], xp01, wv1, accB[0]); FMA_X2(accB[1], xp23, wv1, accB[1]);
    }
    {
        float bc0 = b_conv[l], bc1 = b_conv[32 + l];
        float v0, v1;
        upk(accA[0], v0, v1);
        g_m[(size_t)(t0 + 0) * DIM + l] = fmaxf(v0 + bc0, 0.0f);
        g_m[(size_t)(t0 + 1) * DIM + l] = fmaxf(v1 + bc0, 0.0f);
        upk(accA[1], v0, v1);
        g_m[(size_t)(t0 + 2) * DIM + l] = fmaxf(v0 + bc0, 0.0f);
        g_m[(size_t)(t0 + 3) * DIM + l] = fmaxf(v1 + bc0, 0.0f);
        upk(accB[0], v0, v1);
        g_m[(size_t)(t0 + 0) * DIM + 32 + l] = fmaxf(v0 + bc1, 0.0f);
        g_m[(size_t)(t0 + 1) * DIM + 32 + l] = fmaxf(v1 + bc1, 0.0f);
        upk(accB[1], v0, v1);
        g_m[(size_t)(t0 + 2) * DIM + 32 + l] = fmaxf(v0 + bc1, 0.0f);
        g_m[(size_t)(t0 + 3) * DIM + 32 + l] = fmaxf(v1 + bc1, 0.0f);
    }
}

// ================= k_grufull: gi + GRU x3 + head =========================
// warp per 4 targets; per-warp smem broadcast buffer [i][q].
__global__ __launch_bounds__(256) void k_grufull(const float* __restrict__ b_ih,
                                                 const float* __restrict__ b_hh,
                                                 const float* __restrict__ b1,
                                                 const float* __restrict__ b2,
                                                 float* __restrict__ out) {
    __shared__ float hb[8][DIM * 4];
    int wid = threadIdx.x >> 5;
    int l = threadIdx.x & 31;
    int gw = (blockIdx.x * 256 + threadIdx.x) >> 5;
    int r0 = gw * 4;
    float* hw = hb[wid];

    float m0[4], m1[4], xt0[4], xt1[4];
#pragma unroll
    for (int q = 0; q < 4; q++) {
        m0[q]  = g_m[(size_t)(r0 + q) * DIM + l];
        m1[q]  = g_m[(size_t)(r0 + q) * DIM + 32 + l];
        xt0[q] = g_h0[(size_t)(r0 + q) * DIM + l];
        xt1[q] = g_h0[(size_t)(r0 + q) * DIM + 32 + l];
    }

    // ---- gi = m @ W_ih^T + b_ih ----
    *reinterpret_cast<float4*>(hw + l * 4)        = make_float4(m0[0], m0[1], m0[2], m0[3]);
    *reinterpret_cast<float4*>(hw + (32 + l) * 4) = make_float4(m1[0], m1[1], m1[2], m1[3]);
    __syncwarp();
    ull gip[6][2];
#pragma unroll
    for (int t = 0; t < 6; t++) { gip[t][0] = 0ull; gip[t][1] = 0ull; }
#pragma unroll 2
    for (int o = 0; o < DIM; o++) {
        float4 mv = *reinterpret_cast<const float4*>(hw + o * 4);
        ull mp01 = pk2(mv.x, mv.y), mp23 = pk2(mv.z, mv.w);
#pragma unroll
        for (int t = 0; t < 6; t++) {
            ull wv = g_Wih_d[o * G3 + l + 32 * t];
            FMA_X2(gip[t][0], mp01, wv, gip[t][0]);
            FMA_X2(gip[t][1], mp23, wv, gip[t][1]);
        }
    }
    float gi[6][4];
#pragma unroll
    for (int t = 0; t < 6; t++) {
        float bi = b_ih[l + 32 * t];
        float v0, v1;
        upk(gip[t][0], v0, v1); gi[t][0] = v0 + bi; gi[t][1] = v1 + bi;
        upk(gip[t][1], v0, v1); gi[t][2] = v0 + bi; gi[t][3] = v1 + bi;
    }

    // ---- GRU x3 ----
    float h0r[4], h1r[4];
#pragma unroll
    for (int q = 0; q < 4; q++) { h0r[q] = xt0[q]; h1r[q] = xt1[q]; }
    float bh[6];
#pragma unroll
    for (int t = 0; t < 6; t++) bh[t] = b_hh[l + 32 * t];

    for (int step = 0; step < 3; step++) {
        __syncwarp();
        *reinterpret_cast<float4*>(hw + l * 4)        = make_float4(h0r[0], h0r[1], h0r[2], h0r[3]);
        *reinterpret_cast<float4*>(hw + (32 + l) * 4) = make_float4(h1r[0], h1r[1], h1r[2], h1r[3]);
        __syncwarp();
        ull ghp[6][2];
#pragma unroll
        for (int t = 0; t < 6; t++) {
            ghp[t][0] = pk2(bh[t], bh[t]);
            ghp[t][1] = ghp[t][0];
        }
#pragma unroll 2
        for (int i = 0; i < DIM; i++) {
            float4 hv = *reinterpret_cast<const float4*>(hw + i * 4);
            ull hp01 = pk2(hv.x, hv.y), hp23 = pk2(hv.z, hv.w);
#pragma unroll
            for (int t = 0; t < 6; t++) {
                ull wv = g_Whh_d[i * G3 + l + 32 * t];
                FMA_X2(ghp[t][0], hp01, wv, ghp[t][0]);
                FMA_X2(ghp[t][1], hp23, wv, ghp[t][1]);
            }
        }
#pragma unroll
        for (int q = 0; q < 4; q++) {
            float ghv[6];
#pragma unroll
            for (int t = 0; t < 6; t++) {
                float lo, hi;
                upk(ghp[t][q >> 1], lo, hi);
                ghv[t] = (q & 1) ? hi : lo;
            }
            float rr0 = sigm(gi[0][q] + ghv[0]);
            float rr1 = sigm(gi[1][q] + ghv[1]);
            float zz0 = sigm(gi[2][q] + ghv[2]);
            float zz1 = sigm(gi[3][q] + ghv[3]);
            float nn0 = tanhx(gi[4][q] + rr0 * ghv[4]);
            float nn1 = tanhx(gi[5][q] + rr1 * ghv[5]);
            h0r[q] = (1.0f - zz0) * nn0 + zz0 * h0r[q];
            h1r[q] = (1.0f - zz1) * nn1 + zz1 * h1r[q];
        }
    }

    // ---- head layer 1: a = relu(h @ W1^T + b1) ----
    __syncwarp();
    *reinterpret_cast<float4*>(hw + l * 4)        = make_float4(h0r[0], h0r[1], h0r[2], h0r[3]);
    *reinterpret_cast<float4*>(hw + (32 + l) * 4) = make_float4(h1r[0], h1r[1], h1r[2], h1r[3]);
    __syncwarp();
    ull aA01 = 0ull, aA23 = 0ull, aB01 = 0ull, aB23 = 0ull;
#pragma unroll 4
    for (int i = 0; i < DIM; i++) {
        float4 hv = *reinterpret_cast<const float4*>(hw + i * 4);
        ull hp01 = pk2(hv.x, hv.y), hp23 = pk2(hv.z, hv.w);
        ull wv0 = g_W1d[i * DIM + l], wv1 = g_W1d[i * DIM + 32 + l];
        FMA_X2(aA01, hp01, wv0, aA01); FMA_X2(aA23, hp23, wv0, aA23);
        FMA_X2(aB01, hp01, wv1, aB01); FMA_X2(aB23, hp23, wv1, aB23);
    }
    float a0[4], a1[4];
    {
        float bb0 = b1[l], bb1 = b1[32 + l];
        float v0, v1;
        upk(aA01, v0, v1); a0[0] = fmaxf(v0 + bb0, 0.0f); a0[1] = fmaxf(v1 + bb0, 0.0f);
        upk(aA23, v0, v1); a0[2] = fmaxf(v0 + bb0, 0.0f); a0[3] = fmaxf(v1 + bb0, 0.0f);
        upk(aB01, v0, v1); a1[0] = fmaxf(v0 + bb1, 0.0f); a1[1] = fmaxf(v1 + bb1, 0.0f);
        upk(aB23, v0, v1); a1[2] = fmaxf(v0 + bb1, 0.0f); a1[3] = fmaxf(v1 + bb1, 0.0f);
    }

    // ---- head layer 2: out = a @ W2^T + b2 ----
    __syncwarp();
    *reinterpret_cast<float4*>(hw + l * 4)        = make_float4(a0[0], a0[1], a0[2], a0[3]);
    *reinterpret_cast<float4*>(hw + (32 + l) * 4) = make_float4(a1[0], a1[1], a1[2], a1[3]);
    __syncwarp();
    ull cA01 = 0ull, cA23 = 0ull, cB01 = 0ull, cB23 = 0ull;
#pragma unroll 4
    for (int i = 0; i < DIM; i++) {
        float4 av = *reinterpret_cast<const float4*>(hw + i * 4);
        ull ap01 = pk2(av.x, av.y), ap23 = pk2(av.z, av.w);
        ull wv0 = g_W2d[i * DIM + l], wv1 = g_W2d[i * DIM + 32 + l];
        FMA_X2(cA01, ap01, wv0, cA01); FMA_X2(cA23, ap23, wv0, cA23);
        FMA_X2(cB01, ap01, wv1, cB01); FMA_X2(cB23, ap23, wv1, cB23);
    }
    {
        float ob0 = b2[l], ob1 = b2[32 + l];
        float v0, v1;
        upk(cA01, v0, v1);
        out[(size_t)(r0 + 0) * DIM + l] = v0 + ob0;
        out[(size_t)(r0 + 1) * DIM + l] = v1 + ob0;
        upk(cA23, v0, v1);
        out[(size_t)(r0 + 2) * DIM + l] = v0 + ob0;
        out[(size_t)(r0 + 3) * DIM + l] = v1 + ob0;
        upk(cB01, v0, v1);
        out[(size_t)(r0 + 0) * DIM + 32 + l] = v0 + ob1;
        out[(size_t)(r0 + 1) * DIM + 32 + l] = v1 + ob1;
        upk(cB23, v0, v1);
        out[(size_t)(r0 + 2) * DIM + 32 + l] = v0 + ob1;
        out[(size_t)(r0 + 3) * DIM + 32 + l] = v1 + ob1;
    }
}

// ---------------- launch ---------------------------------------------------
extern "C" void kernel_launch(void* const* d_in, const int* in_sizes, int n_in,
                              void* d_out, int out_size) {
    const float* x        = (const float*)d_in[0];
    const int*   edge_src = (const int*)d_in[2];
    const int*   edge_dst = (const int*)d_in[3];
    const int*   edge_ids = (const int*)d_in[4];
    const float* edge_w   = (const float*)d_in[5];
    const float* W0       = (const float*)d_in[6];
    const float* b0       = (const float*)d_in[7];
    const float* A1       = (const float*)d_in[8];
    const float* c1       = (const float*)d_in[9];
    const float* A2       = (const float*)d_in[10];
    const float* c2       = (const float*)d_in[11];
    const float* W_root   = (const float*)d_in[12];
    const float* b_conv   = (const float*)d_in[13];
    const float* W_ih     = (const float*)d_in[14];
    const float* W_hh     = (const float*)d_in[15];
    const float* b_ih     = (const float*)d_in[16];
    const float* b_hh     = (const float*)d_in[17];
    const float* W1       = (const float*)d_in[18];
    const float* b1       = (const float*)d_in[19];
    const float* W2       = (const float*)d_in[20];
    const float* b2       = (const float*)d_in[21];
    float* out = (float*)d_out;

    kA<<<128, 256>>>(W0, W_ih, W_hh, W_root, W1, W2, A1, c1);
    kB<<<H0_BLOCKS + 313, 256>>>(x, b0, edge_ids, edge_w, edge_dst);
    kC<<<2, 1024>>>();
    kD<<<CSR_BLOCKS + 4096, 256>>>(edge_src, edge_dst, A1, c1, A2, c2);
    k_gt<<<N_TGT / 4 / 8, 256>>>(b_conv);
    k_grufull<<<N_TGT / 4 / 8, 256>>>(b_ih, b_hh, b1, b2, out);
}

// round 10
// speedup vs baseline: 1.6903x; 1.1702x over previous
#include <cuda_runtime.h>
#include <math.h>

#define N_SRC  80000
#define N_TGT  20000
#define E_NUM  80000
#define IN_DIM 128
#define DIM    64
#define EH     128
#define G3     192
#define NK     129
#define MAXU   2

typedef unsigned long long ull;

__device__ __forceinline__ ull pk2(float lo, float hi) {
    ull r; asm("mov.b64 %0, {%1,%2};" : "=l"(r) : "f"(lo), "f"(hi)); return r;
}
__device__ __forceinline__ void upk(ull v, float& lo, float& hi) {
    asm("mov.b64 {%0,%1}, %2;" : "=f"(lo), "=f"(hi) : "l"(v));
}
#define FMA_X2(d, a, b, c) asm("fma.rn.f32x2 %0, %1, %2, %3;" : "=l"(d) : "l"(a), "l"(b), "l"(c))
#define MUL_X2(d, a, b)    asm("mul.rn.f32x2 %0, %1, %2;"     : "=l"(d) : "l"(a), "l"(b))

__device__ __forceinline__ float sigm(float x)  { return __fdividef(1.0f, 1.0f + __expf(-x)); }
__device__ __forceinline__ float tanhx(float x) { return 1.0f - __fdividef(2.0f, 1.0f + __expf(2.0f * x)); }

// ---------------- scratch ------------------------------------------------
__device__ float g_h0[N_SRC * DIM];
__device__ float g_m[N_TGT * DIM];
__device__ float g_M[NK][DIM * DIM];
__device__ float g_P[NK][DIM * DIM];
__device__ float g_T[NK][DIM * 128];     // packed: [i][lane] = {M_lo,M_hi,P_lo,P_hi}
__device__ float g_thr[EH];
__device__ unsigned char g_act[NK][EH];
__device__ int   g_kedge[E_NUM];
__device__ float g_aedge[E_NUM];
__device__ int   g_used[NK];
__device__ int   g_slotmap[NK];
__device__ int   g_slotk[MAXU];
__device__ int   g_usedlist[NK];
__device__ int   g_usedcnt;
__device__ int   g_nslots;
__device__ int   g_deg[N_TGT];
__device__ int   g_off[N_TGT];
__device__ int   g_cur[N_TGT];
__device__ uint2 g_ce[E_NUM];            // {word, float-bits a}
// paired weight tables: [..]*2 ull, loaded as ulonglong2 (one LDG.128 = 2 packed operands)
__device__ ull   g_W0q[IN_DIM * 32];             // ((i>>1)*32+j)*2+(i&1)
__device__ ull   g_Wih_q[DIM * 3 * 64];          // ((o*3+(t>>1))*32+l)*2+(t&1)
__device__ ull   g_Whh_q[DIM * 3 * 64];
__device__ ull   g_Wr_q[DIM * 64];               // (i*32+(o&31))*2+(o>>5)
__device__ ull   g_W1q[DIM * 64];
__device__ ull   g_W2q[DIM * 64];

// ================= kA: zero + prep + setup (merged) ======================
__global__ __launch_bounds__(256) void kA(const float* __restrict__ W0,
                                          const float* __restrict__ Wih,
                                          const float* __restrict__ Whh,
                                          const float* __restrict__ Wr,
                                          const float* __restrict__ W1,
                                          const float* __restrict__ W2,
                                          const float* __restrict__ A1,
                                          const float* __restrict__ c1) {
    int b = blockIdx.x;
    int t = threadIdx.x;
    if (b < 79) {                               // zero
        int idx = b * 256 + t;
        if (idx < N_TGT) g_deg[idx] = 0;
        if (idx < NK)    g_used[idx] = 0;
        return;
    }
    if (b < 127) {                              // prep
        int idx = (b - 79) * 256 + t;
        if (idx < IN_DIM * 32) {                // W0 pairs: i 0..127, j 0..31
            int i = idx >> 5, j = idx & 31;
            float wa = W0[(2 * j) * IN_DIM + i];
            float wb = W0[(2 * j + 1) * IN_DIM + i];
            g_W0q[((i >> 1) * 32 + j) * 2 + (i & 1)] = pk2(wa, wb);
        }
        if (idx < DIM * G3) {                   // Wih/Whh: o 0..63, g 0..191
            int o = idx / G3, g = idx % G3;
            int l = g & 31, tt = g >> 5;
            int pos = ((o * 3 + (tt >> 1)) * 32 + l) * 2 + (tt & 1);
            float wi = Wih[g * DIM + o]; g_Wih_q[pos] = pk2(wi, wi);
            float wh = Whh[g * DIM + o]; g_Whh_q[pos] = pk2(wh, wh);
        }
        if (idx < DIM * DIM) {                  // Wr/W1/W2: i, o
            int i = idx / DIM, o = idx % DIM;
            int pos = (i * 32 + (o & 31)) * 2 + (o >> 5);
            float wr = Wr[i * DIM + o];  g_Wr_q[pos] = pk2(wr, wr);
            float w1 = W1[o * DIM + i];  g_W1q[pos] = pk2(w1, w1);
            float w2 = W2[o * DIM + i];  g_W2q[pos] = pk2(w2, w2);
        }
        return;
    }
    // setup (1 block, threads < 128)
    __shared__ float ts[EH], sorted[EH];
    if (t >= EH) return;
    int j = t;
    float s = A1[j];
    float c = c1[j];
    float th = (s != 0.0f) ? (-c / s) : 2.0e30f;
    ts[j] = th;
    __syncwarp();
    __syncthreads();
    int rank = 0;
    for (int k = 0; k < EH; k++) {
        float tk = ts[k];
        rank += (tk < th) || (tk == th && k < j);
    }
    sorted[rank] = th;
    __syncthreads();
    g_thr[j] = sorted[j];
    const float BIGT = 1.0e29f;
    for (int k = 0; k < NK; k++) {
        float left  = (k > 0)  ? sorted[k - 1] : -2.0e30f;
        float right = (k < EH) ? sorted[k]     :  2.0e30f;
        bool linf = (left <= -BIGT), rinf = (right >= BIGT);
        float rep;
        if (linf && rinf)      rep = 0.0f;
        else if (linf)         rep = right - 1.0f;
        else if (rinf)         rep = left + 1.0f;
        else                   rep = 0.5f * (left + right);
        g_act[k][j] = (s * rep + c > 0.0f) ? 1 : 0;
    }
}

// ================= kB: h0 + edgek (merged) ===============================
#define H0_BLOCKS (N_SRC / 32)   // 2500
__global__ __launch_bounds__(256) void kB(const float* __restrict__ x,
                                          const float* __restrict__ b0,
                                          const int* __restrict__ eids,
                                          const float* __restrict__ ew,
                                          const int* __restrict__ edst) {
    __shared__ float sthr[EH];
    if (blockIdx.x < H0_BLOCKS) {
        int j  = threadIdx.x & 31;
        int gq = threadIdx.x >> 5;
        int row0 = blockIdx.x * 32 + gq * 4;
        ull acc[4] = {0ull, 0ull, 0ull, 0ull};
#pragma unroll 4
        for (int ii = 0; ii < IN_DIM / 4; ii++) {
            float4 xv0 = *reinterpret_cast<const float4*>(x + (size_t)(row0 + 0) * IN_DIM + ii * 4);
            float4 xv1 = *reinterpret_cast<const float4*>(x + (size_t)(row0 + 1) * IN_DIM + ii * 4);
            float4 xv2 = *reinterpret_cast<const float4*>(x + (size_t)(row0 + 2) * IN_DIM + ii * 4);
            float4 xv3 = *reinterpret_cast<const float4*>(x + (size_t)(row0 + 3) * IN_DIM + ii * 4);
            ulonglong2 wA = *reinterpret_cast<const ulonglong2*>(g_W0q + ((ii * 2 + 0) * 32 + j) * 2);
            ulonglong2 wB = *reinterpret_cast<const ulonglong2*>(g_W0q + ((ii * 2 + 1) * 32 + j) * 2);
#define H0_STEP(comp, wv)                                          \
            {                                                      \
                FMA_X2(acc[0], pk2(xv0.comp, xv0.comp), wv, acc[0]);\
                FMA_X2(acc[1], pk2(xv1.comp, xv1.comp), wv, acc[1]);\
                FMA_X2(acc[2], pk2(xv2.comp, xv2.comp), wv, acc[2]);\
                FMA_X2(acc[3], pk2(xv3.comp, xv3.comp), wv, acc[3]);\
            }
            H0_STEP(x, wA.x) H0_STEP(y, wA.y) H0_STEP(z, wB.x) H0_STEP(w, wB.y)
#undef H0_STEP
        }
        float ba = b0[2 * j], bb = b0[2 * j + 1];
#pragma unroll
        for (int r = 0; r < 4; r++) {
            float lo, hi;
            upk(acc[r], lo, hi);
            float2 v;
            v.x = fmaxf(lo + ba, 0.0f);
            v.y = fmaxf(hi + bb, 0.0f);
            *reinterpret_cast<float2*>(g_h0 + (size_t)(row0 + r) * DIM + 2 * j) = v;
        }
    } else {
        if (threadIdx.x < EH) sthr[threadIdx.x] = g_thr[threadIdx.x];
        __syncthreads();
        int e = (blockIdx.x - H0_BLOCKS) * 256 + threadIdx.x;
        if (e >= E_NUM) return;
        float a = ew[eids[e]];
        int k = 0;
#pragma unroll
        for (int j = 0; j < EH; j++) k += (sthr[j] < a) ? 1 : 0;
        g_kedge[e] = k;
        g_aedge[e] = a;
        g_used[k]  = 1;
        atomicAdd(&g_deg[edst[e]], 1);
    }
}

// ================= kC: scan (block 0) + slots (block 1) ==================
__global__ __launch_bounds__(1024) void kC() {
    if (blockIdx.x == 0) {
        __shared__ int wsum[32];
        int t = threadIdx.x;
        int start = t * 20;
        int s = 0;
#pragma unroll
        for (int i = 0; i < 20; i++) {
            int idx = start + i;
            if (idx < N_TGT) s += g_deg[idx];
        }
        int lane = t & 31, wid = t >> 5;
        int v = s;
#pragma unroll
        for (int off = 1; off < 32; off <<= 1) {
            int n = __shfl_up_sync(0xffffffffu, v, off);
            if (lane >= off) v += n;
        }
        if (lane == 31) wsum[wid] = v;
        __syncthreads();
        if (wid == 0) {
            int w = wsum[lane];
#pragma unroll
            for (int off = 1; off < 32; off <<= 1) {
                int n = __shfl_up_sync(0xffffffffu, w, off);
                if (lane >= off) w += n;
            }
            wsum[lane] = w;
        }
        __syncthreads();
        int excl = (v - s) + ((wid > 0) ? wsum[wid - 1] : 0);
        int run = excl;
#pragma unroll
        for (int i = 0; i < 20; i++) {
            int idx = start + i;
            if (idx < N_TGT) {
                g_off[idx] = run;
                g_cur[idx] = run;
                run += g_deg[idx];
            }
        }
    } else {
        if (threadIdx.x == 0) {
            int ns = 0;
            for (int k = 0; k < NK; k++) {
                g_slotmap[k] = -1;
                if (g_used[k]) {
                    if (ns < MAXU) { g_slotmap[k] = ns; g_slotk[ns] = k; }
                    g_usedlist[ns] = k;
                    ns++;
                }
            }
            g_usedcnt = ns;
            g_nslots = (ns < MAXU) ? ns : MAXU;
        }
    }
}

// ================= kD: csr + tables (merged) =============================
#define CSR_BLOCKS 313
#define TB_Y 2
__global__ __launch_bounds__(256) void kD(const int* __restrict__ esrc,
                                          const int* __restrict__ edst,
                                          const float* __restrict__ A1,
                                          const float* __restrict__ c1,
                                          const float* __restrict__ A2,
                                          const float* __restrict__ c2) {
    __shared__ float hs[EH], h2s[EH];
    if (blockIdx.x < CSR_BLOCKS) {
        int e = blockIdx.x * 256 + threadIdx.x;
        if (e >= E_NUM) return;
        int dst = edst[e];
        int pos = atomicAdd(&g_cur[dst], 1);
        int k = g_kedge[e];
        int sm = g_slotmap[k];
        unsigned sc = (sm >= 0) ? (unsigned)sm : 7u;
        uint2 ce;
        ce.x = (unsigned)esrc[e] | ((unsigned)k << 17) | (sc << 25);
        ce.y = __float_as_uint(g_aedge[e]);
        g_ce[pos] = ce;
    } else {
        int bb = blockIdx.x - CSR_BLOCKS;      // 0..(512*TB_Y-1)
        int bx = bb & 511;
        int by = bb >> 9;
        int cnt = g_usedcnt;
        int t = threadIdx.x;
        for (int y = by; y < cnt; y += TB_Y) {
            int k = g_usedlist[y];
            __syncthreads();
            if (t < EH) {
                float a = g_act[k][t] ? 1.0f : 0.0f;
                hs[t]  = A1[t] * a;
                h2s[t] = c1[t] * a;
            }
            __syncthreads();
            int w = t >> 5, l = t & 31;
            int io = bx * 8 + w;
            const float4 av = *reinterpret_cast<const float4*>(A2 + (size_t)io * EH + l * 4);
            float m = av.x * hs[l * 4] + av.y * hs[l * 4 + 1] + av.z * hs[l * 4 + 2] + av.w * hs[l * 4 + 3];
            float p = av.x * h2s[l * 4] + av.y * h2s[l * 4 + 1] + av.z * h2s[l * 4 + 2] + av.w * h2s[l * 4 + 3];
#pragma unroll
            for (int off = 16; off > 0; off >>= 1) {
                m += __shfl_down_sync(0xffffffffu, m, off);
                p += __shfl_down_sync(0xffffffffu, p, off);
            }
            if (l == 0) {
                float pv = c2[io] + p;
                g_M[k][io] = m;
                g_P[k][io] = pv;
                int i = io >> 6, o = io & 63;
                int tb = (i * 32 + (o & 31)) * 4 + ((o >> 5) & 1);
                g_T[k][tb]     = m;
                g_T[k][tb + 2] = pv;
            }
        }
    }
}

// ================= k_gt: gather + transform + conv -> m ==================
__global__ __launch_bounds__(256) void k_gt(const float* __restrict__ b_conv) {
    __shared__ float st[8][64 * 16];
    int wid = threadIdx.x >> 5;
    int l   = threadIdx.x & 31;
    int gw  = (blockIdx.x * 256 + threadIdx.x) >> 5;
    int t0  = gw * 4;
    float* sw = st[wid];
    int ns = g_nslots;

    int offv[4], degv[4];
#pragma unroll
    for (int q = 0; q < 4; q++) { offv[q] = g_off[t0 + q]; degv[q] = g_deg[t0 + q]; }
    int dmax = max(max(degv[0], degv[1]), max(degv[2], degv[3]));

    // pair-layout sums: lane l holds dims (2l, 2l+1) packed
    ull S1p[MAXU][4], S0p[MAXU][4];
#pragma unroll
    for (int s = 0; s < MAXU; s++)
#pragma unroll
        for (int q = 0; q < 4; q++) { S1p[s][q] = 0ull; S0p[s][q] = 0ull; }
    float fbA[4] = {0, 0, 0, 0}, fbB[4] = {0, 0, 0, 0};

    // gather with one-ahead meta prefetch (meta = 1 LDG.64, xs = 1 LDG.64)
    uint2 mv[4];
#pragma unroll
    for (int q = 0; q < 4; q++)
        if (degv[q] > 0) mv[q] = __ldg(&g_ce[offv[q]]);
    for (int j = 0; j < dmax; j++) {
        uint2 mn[4];
#pragma unroll
        for (int q = 0; q < 4; q++)
            if (j + 1 < degv[q]) mn[q] = __ldg(&g_ce[offv[q] + j + 1]);
#pragma unroll
        for (int q = 0; q < 4; q++) {
            if (j < degv[q]) {
                unsigned w = mv[q].x;
                float a = __uint_as_float(mv[q].y);
                int src = (int)(w & 0x1FFFFu);
                unsigned sc = w >> 25;
                float2 xs = __ldg(reinterpret_cast<const float2*>(g_h0 + (size_t)src * DIM + 2 * l));
                ull xsp = pk2(xs.x, xs.y);
                ull axp;
                MUL_X2(axp, xsp, pk2(a, a));
#pragma unroll
                for (int s = 0; s < MAXU; s++) {
                    float sel = (sc == (unsigned)s) ? 1.0f : 0.0f;
                    ull selp = pk2(sel, sel);
                    FMA_X2(S1p[s][q], axp, selp, S1p[s][q]);
                    FMA_X2(S0p[s][q], xsp, selp, S0p[s][q]);
                }
                if (sc == 7u) {                  // exact fallback (rare)
                    int k = (int)((w >> 17) & 0xFFu);
                    const float* __restrict__ M = g_M[k];
                    const float* __restrict__ P = g_P[k];
#pragma unroll 8
                    for (int i = 0; i < DIM; i++) {
                        float xi  = __shfl_sync(0xffffffffu, (i & 1) ? xs.y : xs.x, i >> 1);
                        float axi = a * xi;
                        fbA[q] += axi * M[i * DIM + l]      + xi * P[i * DIM + l];
                        fbB[q] += axi * M[i * DIM + 32 + l] + xi * P[i * DIM + 32 + l];
                    }
                }
            }
        }
#pragma unroll
        for (int q = 0; q < 4; q++) mv[q] = mn[q];
    }

    // stage S dim-major: sw[dim*16 + s*8 + {S1:0..3, S0:4..7}]
#pragma unroll
    for (int s = 0; s < MAXU; s++) {
        float x1[4], y1[4], x0[4], y0[4];
#pragma unroll
        for (int q = 0; q < 4; q++) {
            upk(S1p[s][q], x1[q], y1[q]);
            upk(S0p[s][q], x0[q], y0[q]);
        }
        *reinterpret_cast<float4*>(sw + (2 * l) * 16 + s * 8)         = make_float4(x1[0], x1[1], x1[2], x1[3]);
        *reinterpret_cast<float4*>(sw + (2 * l) * 16 + s * 8 + 4)     = make_float4(x0[0], x0[1], x0[2], x0[3]);
        *reinterpret_cast<float4*>(sw + (2 * l + 1) * 16 + s * 8)     = make_float4(y1[0], y1[1], y1[2], y1[3]);
        *reinterpret_cast<float4*>(sw + (2 * l + 1) * 16 + s * 8 + 4) = make_float4(y0[0], y0[1], y0[2], y0[3]);
    }
    __syncwarp();

    // transform (acc layout: pairs of targets at dims l / 32+l)
    ull accA[2], accB[2];
    accA[0] = pk2(fbA[0], fbA[1]); accA[1] = pk2(fbA[2], fbA[3]);
    accB[0] = pk2(fbB[0], fbB[1]); accB[1] = pk2(fbB[2], fbB[3]);
#pragma unroll
    for (int s = 0; s < MAXU; s++) {
        if (s >= ns) break;
        const float4* __restrict__ Tk = reinterpret_cast<const float4*>(g_T[g_slotk[s]]);
#pragma unroll 4
        for (int i = 0; i < DIM; i++) {
            float4 sv1 = *reinterpret_cast<const float4*>(sw + i * 16 + s * 8);
            float4 sv0 = *reinterpret_cast<const float4*>(sw + i * 16 + s * 8 + 4);
            float4 tv  = __ldg(&Tk[i * 32 + l]);
            ull s1p01 = pk2(sv1.x, sv1.y), s1p23 = pk2(sv1.z, sv1.w);
            ull s0p01 = pk2(sv0.x, sv0.y), s0p23 = pk2(sv0.z, sv0.w);
            FMA_X2(accA[0], s1p01, pk2(tv.x, tv.x), accA[0]);
            FMA_X2(accA[1], s1p23, pk2(tv.x, tv.x), accA[1]);
            FMA_X2(accA[0], s0p01, pk2(tv.z, tv.z), accA[0]);
            FMA_X2(accA[1], s0p23, pk2(tv.z, tv.z), accA[1]);
            FMA_X2(accB[0], s1p01, pk2(tv.y, tv.y), accB[0]);
            FMA_X2(accB[1], s1p23, pk2(tv.y, tv.y), accB[1]);
            FMA_X2(accB[0], s0p01, pk2(tv.w, tv.w), accB[0]);
            FMA_X2(accB[1], s0p23, pk2(tv.w, tv.w), accB[1]);
        }
    }

    // divide by counts
    {
        float i0 = __fdividef(1.0f, fmaxf((float)degv[0], 1.0f));
        float i1 = __fdividef(1.0f, fmaxf((float)degv[1], 1.0f));
        float i2 = __fdividef(1.0f, fmaxf((float)degv[2], 1.0f));
        float i3 = __fdividef(1.0f, fmaxf((float)degv[3], 1.0f));
        float v0, v1;
        upk(accA[0], v0, v1); accA[0] = pk2(v0 * i0, v1 * i1);
        upk(accA[1], v0, v1); accA[1] = pk2(v0 * i2, v1 * i3);
        upk(accB[0], v0, v1); accB[0] = pk2(v0 * i0, v1 * i1);
        upk(accB[1], v0, v1); accB[1] = pk2(v0 * i2, v1 * i3);
    }

    // x_tgt pair-load + dim-major staging + conv root matvec
    float2 xtp[4];
#pragma unroll
    for (int q = 0; q < 4; q++)
        xtp[q] = *reinterpret_cast<const float2*>(g_h0 + (size_t)(t0 + q) * DIM + 2 * l);
    __syncwarp();
    *reinterpret_cast<float4*>(sw + (2 * l) * 4)     = make_float4(xtp[0].x, xtp[1].x, xtp[2].x, xtp[3].x);
    *reinterpret_cast<float4*>(sw + (2 * l + 1) * 4) = make_float4(xtp[0].y, xtp[1].y, xtp[2].y, xtp[3].y);
    __syncwarp();
#pragma unroll 4
    for (int i = 0; i < DIM; i++) {
        float4 xv = *reinterpret_cast<const float4*>(sw + i * 4);
        ulonglong2 wv = *reinterpret_cast<const ulonglong2*>(g_Wr_q + (i * 32 + l) * 2);
        ull xp01 = pk2(xv.x, xv.y), xp23 = pk2(xv.z, xv.w);
        FMA_X2(accA[0], xp01, wv.x, accA[0]); FMA_X2(accA[1], xp23, wv.x, accA[1]);
        FMA_X2(accB[0], xp01, wv.y, accB[0]); FMA_X2(accB[1], xp23, wv.y, accB[1]);
    }
    {
        float bc0 = b_conv[l], bc1 = b_conv[32 + l];
        float v0, v1;
        upk(accA[0], v0, v1);
        g_m[(size_t)(t0 + 0) * DIM + l] = fmaxf(v0 + bc0, 0.0f);
        g_m[(size_t)(t0 + 1) * DIM + l] = fmaxf(v1 + bc0, 0.0f);
        upk(accA[1], v0, v1);
        g_m[(size_t)(t0 + 2) * DIM + l] = fmaxf(v0 + bc0, 0.0f);
        g_m[(size_t)(t0 + 3) * DIM + l] = fmaxf(v1 + bc0, 0.0f);
        upk(accB[0], v0, v1);
        g_m[(size_t)(t0 + 0) * DIM + 32 + l] = fmaxf(v0 + bc1, 0.0f);
        g_m[(size_t)(t0 + 1) * DIM + 32 + l] = fmaxf(v1 + bc1, 0.0f);
        upk(accB[1], v0, v1);
        g_m[(size_t)(t0 + 2) * DIM + 32 + l] = fmaxf(v0 + bc1, 0.0f);
        g_m[(size_t)(t0 + 3) * DIM + 32 + l] = fmaxf(v1 + bc1, 0.0f);
    }
}

// ================= k_grufull: gi + GRU x3 + head =========================
__global__ __launch_bounds__(256) void k_grufull(const float* __restrict__ b_ih,
                                                 const float* __restrict__ b_hh,
                                                 const float* __restrict__ b1,
                                                 const float* __restrict__ b2,
                                                 float* __restrict__ out) {
    __shared__ float hb[8][DIM * 4];
    int wid = threadIdx.x >> 5;
    int l = threadIdx.x & 31;
    int gw = (blockIdx.x * 256 + threadIdx.x) >> 5;
    int r0 = gw * 4;
    float* hw = hb[wid];

    // m pair-load + dim-major staging
    float2 mp[4];
#pragma unroll
    for (int q = 0; q < 4; q++)
        mp[q] = *reinterpret_cast<const float2*>(g_m + (size_t)(r0 + q) * DIM + 2 * l);
    *reinterpret_cast<float4*>(hw + (2 * l) * 4)     = make_float4(mp[0].x, mp[1].x, mp[2].x, mp[3].x);
    *reinterpret_cast<float4*>(hw + (2 * l + 1) * 4) = make_float4(mp[0].y, mp[1].y, mp[2].y, mp[3].y);
    float xt0[4], xt1[4];
#pragma unroll
    for (int q = 0; q < 4; q++) {
        xt0[q] = g_h0[(size_t)(r0 + q) * DIM + l];
        xt1[q] = g_h0[(size_t)(r0 + q) * DIM + 32 + l];
    }
    __syncwarp();

    // gi = m @ W_ih^T + b_ih (3 LDG.128 of paired gates per i)
    ull gip[6][2];
#pragma unroll
    for (int t = 0; t < 6; t++) { gip[t][0] = 0ull; gip[t][1] = 0ull; }
#pragma unroll 2
    for (int o = 0; o < DIM; o++) {
        float4 mv = *reinterpret_cast<const float4*>(hw + o * 4);
        ull mp01 = pk2(mv.x, mv.y), mp23 = pk2(mv.z, mv.w);
#pragma unroll
        for (int tp = 0; tp < 3; tp++) {
            ulonglong2 wv = *reinterpret_cast<const ulonglong2*>(g_Wih_q + ((o * 3 + tp) * 32 + l) * 2);
            FMA_X2(gip[2 * tp][0],     mp01, wv.x, gip[2 * tp][0]);
            FMA_X2(gip[2 * tp][1],     mp23, wv.x, gip[2 * tp][1]);
            FMA_X2(gip[2 * tp + 1][0], mp01, wv.y, gip[2 * tp + 1][0]);
            FMA_X2(gip[2 * tp + 1][1], mp23, wv.y, gip[2 * tp + 1][1]);
        }
    }
    float gi[6][4];
#pragma unroll
    for (int t = 0; t < 6; t++) {
        float bi = b_ih[l + 32 * t];
        float v0, v1;
        upk(gip[t][0], v0, v1); gi[t][0] = v0 + bi; gi[t][1] = v1 + bi;
        upk(gip[t][1], v0, v1); gi[t][2] = v0 + bi; gi[t][3] = v1 + bi;
    }

    // GRU x3
    float h0r[4], h1r[4];
#pragma unroll
    for (int q = 0; q < 4; q++) { h0r[q] = xt0[q]; h1r[q] = xt1[q]; }
    float bh[6];
#pragma unroll
    for (int t = 0; t < 6; t++) bh[t] = b_hh[l + 32 * t];

    for (int step = 0; step < 3; step++) {
        __syncwarp();
        *reinterpret_cast<float4*>(hw + l * 4)        = make_float4(h0r[0], h0r[1], h0r[2], h0r[3]);
        *reinterpret_cast<float4*>(hw + (32 + l) * 4) = make_float4(h1r[0], h1r[1], h1r[2], h1r[3]);
        __syncwarp();
        ull ghp[6][2];
#pragma unroll
        for (int t = 0; t < 6; t++) {
            ghp[t][0] = pk2(bh[t], bh[t]);
            ghp[t][1] = ghp[t][0];
        }
#pragma unroll 2
        for (int i = 0; i < DIM; i++) {
            float4 hv = *reinterpret_cast<const float4*>(hw + i * 4);
            ull hp01 = pk2(hv.x, hv.y), hp23 = pk2(hv.z, hv.w);
#pragma unroll
            for (int tp = 0; tp < 3; tp++) {
                ulonglong2 wv = *reinterpret_cast<const ulonglong2*>(g_Whh_q + ((i * 3 + tp) * 32 + l) * 2);
                FMA_X2(ghp[2 * tp][0],     hp01, wv.x, ghp[2 * tp][0]);
                FMA_X2(ghp[2 * tp][1],     hp23, wv.x, ghp[2 * tp][1]);
                FMA_X2(ghp[2 * tp + 1][0], hp01, wv.y, ghp[2 * tp + 1][0]);
                FMA_X2(ghp[2 * tp + 1][1], hp23, wv.y, ghp[2 * tp + 1][1]);
            }
        }
#pragma unroll
        for (int q = 0; q < 4; q++) {
            float ghv[6];
#pragma unroll
            for (int t = 0; t < 6; t++) {
                float lo, hi;
                upk(ghp[t][q >> 1], lo, hi);
                ghv[t] = (q & 1) ? hi : lo;
            }
            float rr0 = sigm(gi[0][q] + ghv[0]);
            float rr1 = sigm(gi[1][q] + ghv[1]);
            float zz0 = sigm(gi[2][q] + ghv[2]);
            float zz1 = sigm(gi[3][q] + ghv[3]);
            float nn0 = tanhx(gi[4][q] + rr0 * ghv[4]);
            float nn1 = tanhx(gi[5][q] + rr1 * ghv[5]);
            h0r[q] = (1.0f - zz0) * nn0 + zz0 * h0r[q];
            h1r[q] = (1.0f - zz1) * nn1 + zz1 * h1r[q];
        }
    }

    // head layer 1
    __syncwarp();
    *reinterpret_cast<float4*>(hw + l * 4)        = make_float4(h0r[0], h0r[1], h0r[2], h0r[3]);
    *reinterpret_cast<float4*>(hw + (32 + l) * 4) = make_float4(h1r[0], h1r[1], h1r[2], h1r[3]);
    __syncwarp();
    ull aA01 = 0ull, aA23 = 0ull, aB01 = 0ull, aB23 = 0ull;
#pragma unroll 4
    for (int i = 0; i < DIM; i++) {
        float4 hv = *reinterpret_cast<const float4*>(hw + i * 4);
        ull hp01 = pk2(hv.x, hv.y), hp23 = pk2(hv.z, hv.w);
        ulonglong2 wv = *reinterpret_cast<const ulonglong2*>(g_W1q + (i * 32 + l) * 2);
        FMA_X2(aA01, hp01, wv.x, aA01); FMA_X2(aA23, hp23, wv.x, aA23);
        FMA_X2(aB01, hp01, wv.y, aB01); FMA_X2(aB23, hp23, wv.y, aB23);
    }
    float a0[4], a1[4];
    {
        float bb0 = b1[l], bb1 = b1[32 + l];
        float v0, v1;
        upk(aA01, v0, v1); a0[0] = fmaxf(v0 + bb0, 0.0f); a0[1] = fmaxf(v1 + bb0, 0.0f);
        upk(aA23, v0, v1); a0[2] = fmaxf(v0 + bb0, 0.0f); a0[3] = fmaxf(v1 + bb0, 0.0f);
        upk(aB01, v0, v1); a1[0] = fmaxf(v0 + bb1, 0.0f); a1[1] = fmaxf(v1 + bb1, 0.0f);
        upk(aB23, v0, v1); a1[2] = fmaxf(v0 + bb1, 0.0f); a1[3] = fmaxf(v1 + bb1, 0.0f);
    }

    // head layer 2
    __syncwarp();
    *reinterpret_cast<float4*>(hw + l * 4)        = make_float4(a0[0], a0[1], a0[2], a0[3]);
    *reinterpret_cast<float4*>(hw + (32 + l) * 4) = make_float4(a1[0], a1[1], a1[2], a1[3]);
    __syncwarp();
    ull cA01 = 0ull, cA23 = 0ull, cB01 = 0ull, cB23 = 0ull;
#pragma unroll 4
    for (int i = 0; i < DIM; i++) {
        float4 av = *reinterpret_cast<const float4*>(hw + i * 4);
        ull ap01 = pk2(av.x, av.y), ap23 = pk2(av.z, av.w);
        ulonglong2 wv = *reinterpret_cast<const ulonglong2*>(g_W2q + (i * 32 + l) * 2);
        FMA_X2(cA01, ap01, wv.x, cA01); FMA_X2(cA23, ap23, wv.x, cA23);
        FMA_X2(cB01, ap01, wv.y, cB01); FMA_X2(cB23, ap23, wv.y, cB23);
    }
    {
        float ob0 = b2[l], ob1 = b2[32 + l];
        float v0, v1;
        upk(cA01, v0, v1);
        out[(size_t)(r0 + 0) * DIM + l] = v0 + ob0;
        out[(size_t)(r0 + 1) * DIM + l] = v1 + ob0;
        upk(cA23, v0, v1);
        out[(size_t)(r0 + 2) * DIM + l] = v0 + ob0;
        out[(size_t)(r0 + 3) * DIM + l] = v1 + ob0;
        upk(cB01, v0, v1);
        out[(size_t)(r0 + 0) * DIM + 32 + l] = v0 + ob1;
        out[(size_t)(r0 + 1) * DIM + 32 + l] = v1 + ob1;
        upk(cB23, v0, v1);
        out[(size_t)(r0 + 2) * DIM + 32 + l] = v0 + ob1;
        out[(size_t)(r0 + 3) * DIM + 32 + l] = v1 + ob1;
    }
}

// ---------------- launch ---------------------------------------------------
extern "C" void kernel_launch(void* const* d_in, const int* in_sizes, int n_in,
                              void* d_out, int out_size) {
    const float* x        = (const float*)d_in[0];
    const int*   edge_src = (const int*)d_in[2];
    const int*   edge_dst = (const int*)d_in[3];
    const int*   edge_ids = (const int*)d_in[4];
    const float* edge_w   = (const float*)d_in[5];
    const float* W0       = (const float*)d_in[6];
    const float* b0       = (const float*)d_in[7];
    const float* A1       = (const float*)d_in[8];
    const float* c1       = (const float*)d_in[9];
    const float* A2       = (const float*)d_in[10];
    const float* c2       = (const float*)d_in[11];
    const float* W_root   = (const float*)d_in[12];
    const float* b_conv   = (const float*)d_in[13];
    const float* W_ih     = (const float*)d_in[14];
    const float* W_hh     = (const float*)d_in[15];
    const float* b_ih     = (const float*)d_in[16];
    const float* b_hh     = (const float*)d_in[17];
    const float* W1       = (const float*)d_in[18];
    const float* b1       = (const float*)d_in[19];
    const float* W2       = (const float*)d_in[20];
    const float* b2       = (const float*)d_in[21];
    float* out = (float*)d_out;

    kA<<<128, 256>>>(W0, W_ih, W_hh, W_root, W1, W2, A1, c1);
    kB<<<H0_BLOCKS + 313, 256>>>(x, b0, edge_ids, edge_w, edge_dst);
    kC<<<2, 1024>>>();
    kD<<<CSR_BLOCKS + 512 * TB_Y, 256>>>(edge_src, edge_dst, A1, c1, A2, c2);
    k_gt<<<N_TGT / 4 / 8, 256>>>(b_conv);
    k_grufull<<<N_TGT / 4 / 8, 256>>>(b_ih, b_hh, b1, b2, out);
}

// round 11
// speedup vs baseline: 1.7122x; 1.0130x over previous
#include <cuda_runtime.h>
#include <math.h>

#define N_SRC  80000
#define N_TGT  20000
#define E_NUM  80000
#define IN_DIM 128
#define DIM    64
#define EH     128
#define G3     192
#define NK     129
#define MAXU   2

typedef unsigned long long ull;

__device__ __forceinline__ ull pk2(float lo, float hi) {
    ull r; asm("mov.b64 %0, {%1,%2};" : "=l"(r) : "f"(lo), "f"(hi)); return r;
}
__device__ __forceinline__ void upk(ull v, float& lo, float& hi) {
    asm("mov.b64 {%0,%1}, %2;" : "=f"(lo), "=f"(hi) : "l"(v));
}
#define FMA_X2(d, a, b, c) asm("fma.rn.f32x2 %0, %1, %2, %3;" : "=l"(d) : "l"(a), "l"(b), "l"(c))
#define MUL_X2(d, a, b)    asm("mul.rn.f32x2 %0, %1, %2;"     : "=l"(d) : "l"(a), "l"(b))

__device__ __forceinline__ float sigm(float x)  { return __fdividef(1.0f, 1.0f + __expf(-x)); }
__device__ __forceinline__ float tanhx(float x) { return 1.0f - __fdividef(2.0f, 1.0f + __expf(2.0f * x)); }

// ---------------- scratch ------------------------------------------------
__device__ float g_h0[N_SRC * DIM];
__device__ float g_M[NK][DIM * DIM];
__device__ float g_P[NK][DIM * DIM];
__device__ float g_T[NK][DIM * 128];     // packed: [i][lane] = {M_lo,M_hi,P_lo,P_hi}
__device__ float g_thr[EH];
__device__ unsigned char g_act[NK][EH];
__device__ int   g_kedge[E_NUM];
__device__ float g_aedge[E_NUM];
__device__ int   g_used[NK];
__device__ int   g_slotmap[NK];
__device__ int   g_slotk[MAXU];
__device__ int   g_usedlist[NK];
__device__ int   g_usedcnt;
__device__ int   g_nslots;
__device__ int   g_deg[N_TGT];
__device__ int   g_off[N_TGT];
__device__ int   g_cur[N_TGT];
__device__ uint2 g_ce[E_NUM];            // {word, float-bits a}
// paired weight tables (ulonglong2 loads: one LDG.128 = 2 packed operands)
__device__ ull   g_W0q[IN_DIM * 32];
__device__ ull   g_Wih_q[DIM * 3 * 64];
__device__ ull   g_Whh_q[DIM * 3 * 64];
__device__ ull   g_Wr_q[DIM * 64];
__device__ ull   g_W1q[DIM * 64];
__device__ ull   g_W2q[DIM * 64];

// ================= kA: zero + prep + setup (merged) ======================
__global__ __launch_bounds__(256) void kA(const float* __restrict__ W0,
                                          const float* __restrict__ Wih,
                                          const float* __restrict__ Whh,
                                          const float* __restrict__ Wr,
                                          const float* __restrict__ W1,
                                          const float* __restrict__ W2,
                                          const float* __restrict__ A1,
                                          const float* __restrict__ c1) {
    int b = blockIdx.x;
    int t = threadIdx.x;
    if (b < 79) {                               // zero
        int idx = b * 256 + t;
        if (idx < N_TGT) g_deg[idx] = 0;
        if (idx < NK)    g_used[idx] = 0;
        return;
    }
    if (b < 127) {                              // prep
        int idx = (b - 79) * 256 + t;
        if (idx < IN_DIM * 32) {
            int i = idx >> 5, j = idx & 31;
            float wa = W0[(2 * j) * IN_DIM + i];
            float wb = W0[(2 * j + 1) * IN_DIM + i];
            g_W0q[((i >> 1) * 32 + j) * 2 + (i & 1)] = pk2(wa, wb);
        }
        if (idx < DIM * G3) {
            int o = idx / G3, g = idx % G3;
            int l = g & 31, tt = g >> 5;
            int pos = ((o * 3 + (tt >> 1)) * 32 + l) * 2 + (tt & 1);
            float wi = Wih[g * DIM + o]; g_Wih_q[pos] = pk2(wi, wi);
            float wh = Whh[g * DIM + o]; g_Whh_q[pos] = pk2(wh, wh);
        }
        if (idx < DIM * DIM) {
            int i = idx / DIM, o = idx % DIM;
            int pos = (i * 32 + (o & 31)) * 2 + (o >> 5);
            float wr = Wr[i * DIM + o];  g_Wr_q[pos] = pk2(wr, wr);
            float w1 = W1[o * DIM + i];  g_W1q[pos] = pk2(w1, w1);
            float w2 = W2[o * DIM + i];  g_W2q[pos] = pk2(w2, w2);
        }
        return;
    }
    // setup (1 block, threads < 128)
    __shared__ float ts[EH], sorted[EH];
    if (t >= EH) return;
    int j = t;
    float s = A1[j];
    float c = c1[j];
    float th = (s != 0.0f) ? (-c / s) : 2.0e30f;
    ts[j] = th;
    __syncwarp();
    __syncthreads();
    int rank = 0;
    for (int k = 0; k < EH; k++) {
        float tk = ts[k];
        rank += (tk < th) || (tk == th && k < j);
    }
    sorted[rank] = th;
    __syncthreads();
    g_thr[j] = sorted[j];
    const float BIGT = 1.0e29f;
    for (int k = 0; k < NK; k++) {
        float left  = (k > 0)  ? sorted[k - 1] : -2.0e30f;
        float right = (k < EH) ? sorted[k]     :  2.0e30f;
        bool linf = (left <= -BIGT), rinf = (right >= BIGT);
        float rep;
        if (linf && rinf)      rep = 0.0f;
        else if (linf)         rep = right - 1.0f;
        else if (rinf)         rep = left + 1.0f;
        else                   rep = 0.5f * (left + right);
        g_act[k][j] = (s * rep + c > 0.0f) ? 1 : 0;
    }
}

// ================= kB: h0 + edgek (merged) ===============================
#define H0_BLOCKS (N_SRC / 32)   // 2500
__global__ __launch_bounds__(256) void kB(const float* __restrict__ x,
                                          const float* __restrict__ b0,
                                          const int* __restrict__ eids,
                                          const float* __restrict__ ew,
                                          const int* __restrict__ edst) {
    __shared__ float sthr[EH];
    if (blockIdx.x < H0_BLOCKS) {
        int j  = threadIdx.x & 31;
        int gq = threadIdx.x >> 5;
        int row0 = blockIdx.x * 32 + gq * 4;
        ull acc[4] = {0ull, 0ull, 0ull, 0ull};
#pragma unroll 4
        for (int ii = 0; ii < IN_DIM / 4; ii++) {
            float4 xv0 = *reinterpret_cast<const float4*>(x + (size_t)(row0 + 0) * IN_DIM + ii * 4);
            float4 xv1 = *reinterpret_cast<const float4*>(x + (size_t)(row0 + 1) * IN_DIM + ii * 4);
            float4 xv2 = *reinterpret_cast<const float4*>(x + (size_t)(row0 + 2) * IN_DIM + ii * 4);
            float4 xv3 = *reinterpret_cast<const float4*>(x + (size_t)(row0 + 3) * IN_DIM + ii * 4);
            ulonglong2 wA = *reinterpret_cast<const ulonglong2*>(g_W0q + ((ii * 2 + 0) * 32 + j) * 2);
            ulonglong2 wB = *reinterpret_cast<const ulonglong2*>(g_W0q + ((ii * 2 + 1) * 32 + j) * 2);
#define H0_STEP(comp, wv)                                          \
            {                                                      \
                FMA_X2(acc[0], pk2(xv0.comp, xv0.comp), wv, acc[0]);\
                FMA_X2(acc[1], pk2(xv1.comp, xv1.comp), wv, acc[1]);\
                FMA_X2(acc[2], pk2(xv2.comp, xv2.comp), wv, acc[2]);\
                FMA_X2(acc[3], pk2(xv3.comp, xv3.comp), wv, acc[3]);\
            }
            H0_STEP(x, wA.x) H0_STEP(y, wA.y) H0_STEP(z, wB.x) H0_STEP(w, wB.y)
#undef H0_STEP
        }
        float ba = b0[2 * j], bb = b0[2 * j + 1];
#pragma unroll
        for (int r = 0; r < 4; r++) {
            float lo, hi;
            upk(acc[r], lo, hi);
            float2 v;
            v.x = fmaxf(lo + ba, 0.0f);
            v.y = fmaxf(hi + bb, 0.0f);
            *reinterpret_cast<float2*>(g_h0 + (size_t)(row0 + r) * DIM + 2 * j) = v;
        }
    } else {
        if (threadIdx.x < EH) sthr[threadIdx.x] = g_thr[threadIdx.x];
        __syncthreads();
        int e = (blockIdx.x - H0_BLOCKS) * 256 + threadIdx.x;
        if (e >= E_NUM) return;
        float a = ew[eids[e]];
        int k = 0;
#pragma unroll
        for (int j = 0; j < EH; j++) k += (sthr[j] < a) ? 1 : 0;
        g_kedge[e] = k;
        g_aedge[e] = a;
        g_used[k]  = 1;
        atomicAdd(&g_deg[edst[e]], 1);
    }
}

// ================= kC: scan (block 0) + slots (block 1) ==================
__global__ __launch_bounds__(1024) void kC() {
    if (blockIdx.x == 0) {
        __shared__ int wsum[32];
        int t = threadIdx.x;
        int start = t * 20;
        int s = 0;
#pragma unroll
        for (int i = 0; i < 20; i++) {
            int idx = start + i;
            if (idx < N_TGT) s += g_deg[idx];
        }
        int lane = t & 31, wid = t >> 5;
        int v = s;
#pragma unroll
        for (int off = 1; off < 32; off <<= 1) {
            int n = __shfl_up_sync(0xffffffffu, v, off);
            if (lane >= off) v += n;
        }
        if (lane == 31) wsum[wid] = v;
        __syncthreads();
        if (wid == 0) {
            int w = wsum[lane];
#pragma unroll
            for (int off = 1; off < 32; off <<= 1) {
                int n = __shfl_up_sync(0xffffffffu, w, off);
                if (lane >= off) w += n;
            }
            wsum[lane] = w;
        }
        __syncthreads();
        int excl = (v - s) + ((wid > 0) ? wsum[wid - 1] : 0);
        int run = excl;
#pragma unroll
        for (int i = 0; i < 20; i++) {
            int idx = start + i;
            if (idx < N_TGT) {
                g_off[idx] = run;
                g_cur[idx] = run;
                run += g_deg[idx];
            }
        }
    } else {
        if (threadIdx.x == 0) {
            int ns = 0;
            for (int k = 0; k < NK; k++) {
                g_slotmap[k] = -1;
                if (g_used[k]) {
                    if (ns < MAXU) { g_slotmap[k] = ns; g_slotk[ns] = k; }
                    g_usedlist[ns] = k;
                    ns++;
                }
            }
            g_usedcnt = ns;
            g_nslots = (ns < MAXU) ? ns : MAXU;
        }
    }
}

// ================= kD: csr + tables (merged) =============================
#define CSR_BLOCKS 313
#define TB_Y 2
__global__ __launch_bounds__(256) void kD(const int* __restrict__ esrc,
                                          const int* __restrict__ edst,
                                          const float* __restrict__ A1,
                                          const float* __restrict__ c1,
                                          const float* __restrict__ A2,
                                          const float* __restrict__ c2) {
    __shared__ float hs[EH], h2s[EH];
    if (blockIdx.x < CSR_BLOCKS) {
        int e = blockIdx.x * 256 + threadIdx.x;
        if (e >= E_NUM) return;
        int dst = edst[e];
        int pos = atomicAdd(&g_cur[dst], 1);
        int k = g_kedge[e];
        int sm = g_slotmap[k];
        unsigned sc = (sm >= 0) ? (unsigned)sm : 7u;
        uint2 ce;
        ce.x = (unsigned)esrc[e] | ((unsigned)k << 17) | (sc << 25);
        ce.y = __float_as_uint(g_aedge[e]);
        g_ce[pos] = ce;
    } else {
        int bb = blockIdx.x - CSR_BLOCKS;
        int bx = bb & 511;
        int by = bb >> 9;
        int cnt = g_usedcnt;
        int t = threadIdx.x;
        for (int y = by; y < cnt; y += TB_Y) {
            int k = g_usedlist[y];
            __syncthreads();
            if (t < EH) {
                float a = g_act[k][t] ? 1.0f : 0.0f;
                hs[t]  = A1[t] * a;
                h2s[t] = c1[t] * a;
            }
            __syncthreads();
            int w = t >> 5, l = t & 31;
            int io = bx * 8 + w;
            const float4 av = *reinterpret_cast<const float4*>(A2 + (size_t)io * EH + l * 4);
            float m = av.x * hs[l * 4] + av.y * hs[l * 4 + 1] + av.z * hs[l * 4 + 2] + av.w * hs[l * 4 + 3];
            float p = av.x * h2s[l * 4] + av.y * h2s[l * 4 + 1] + av.z * h2s[l * 4 + 2] + av.w * h2s[l * 4 + 3];
#pragma unroll
            for (int off = 16; off > 0; off >>= 1) {
                m += __shfl_down_sync(0xffffffffu, m, off);
                p += __shfl_down_sync(0xffffffffu, p, off);
            }
            if (l == 0) {
                float pv = c2[io] + p;
                g_M[k][io] = m;
                g_P[k][io] = pv;
                int i = io >> 6, o = io & 63;
                int tb = (i * 32 + (o & 31)) * 4 + ((o >> 5) & 1);
                g_T[k][tb]     = m;
                g_T[k][tb + 2] = pv;
            }
        }
    }
}

// ================= k_tail: gather+transform+conv+gi+GRU+head =============
// warp per 4 targets, fully fused (warp-private chain: m feeds same warp's GRU)
__global__ __launch_bounds__(256, 2) void k_tail(const float* __restrict__ b_conv,
                                                 const float* __restrict__ b_ih,
                                                 const float* __restrict__ b_hh,
                                                 const float* __restrict__ b1,
                                                 const float* __restrict__ b2,
                                                 float* __restrict__ out) {
    __shared__ float st[8][64 * 16];
    int wid = threadIdx.x >> 5;
    int l   = threadIdx.x & 31;
    int gw  = (blockIdx.x * 256 + threadIdx.x) >> 5;
    int t0  = gw * 4;
    float* sw = st[wid];
    int ns = g_nslots;

    int offv[4], degv[4];
#pragma unroll
    for (int q = 0; q < 4; q++) { offv[q] = g_off[t0 + q]; degv[q] = g_deg[t0 + q]; }
    int dmax = max(max(degv[0], degv[1]), max(degv[2], degv[3]));

    // pair-layout sums: lane l holds dims (2l, 2l+1) packed
    ull S1p[MAXU][4], S0p[MAXU][4];
#pragma unroll
    for (int s = 0; s < MAXU; s++)
#pragma unroll
        for (int q = 0; q < 4; q++) { S1p[s][q] = 0ull; S0p[s][q] = 0ull; }
    float fbA[4] = {0, 0, 0, 0}, fbB[4] = {0, 0, 0, 0};

    // ---- gather: depth-2 meta, depth-1 xs software pipeline ----
    uint2 mA[4], mB[4];
    float2 xA[4];
#pragma unroll
    for (int q = 0; q < 4; q++) if (degv[q] > 0) mA[q] = __ldg(&g_ce[offv[q]]);
#pragma unroll
    for (int q = 0; q < 4; q++) if (degv[q] > 1) mB[q] = __ldg(&g_ce[offv[q] + 1]);
#pragma unroll
    for (int q = 0; q < 4; q++)
        if (degv[q] > 0) {
            int s = (int)(mA[q].x & 0x1FFFFu);
            xA[q] = __ldg(reinterpret_cast<const float2*>(g_h0 + (size_t)s * DIM + 2 * l));
        }
    for (int j = 0; j < dmax; j++) {
        uint2 mC[4]; float2 xB[4];
#pragma unroll
        for (int q = 0; q < 4; q++)
            if (j + 2 < degv[q]) mC[q] = __ldg(&g_ce[offv[q] + j + 2]);
#pragma unroll
        for (int q = 0; q < 4; q++)
            if (j + 1 < degv[q]) {
                int s = (int)(mB[q].x & 0x1FFFFu);
                xB[q] = __ldg(reinterpret_cast<const float2*>(g_h0 + (size_t)s * DIM + 2 * l));
            }
#pragma unroll
        for (int q = 0; q < 4; q++) {
            if (j < degv[q]) {
                unsigned w = mA[q].x;
                float a = __uint_as_float(mA[q].y);
                unsigned sc = w >> 25;
                ull xsp = pk2(xA[q].x, xA[q].y);
                ull axp;
                MUL_X2(axp, xsp, pk2(a, a));
#pragma unroll
                for (int s = 0; s < MAXU; s++) {
                    float sel = (sc == (unsigned)s) ? 1.0f : 0.0f;
                    ull selp = pk2(sel, sel);
                    FMA_X2(S1p[s][q], axp, selp, S1p[s][q]);
                    FMA_X2(S0p[s][q], xsp, selp, S0p[s][q]);
                }
                if (sc == 7u) {                  // exact fallback (rare)
                    int k = (int)((w >> 17) & 0xFFu);
                    const float* __restrict__ M = g_M[k];
                    const float* __restrict__ P = g_P[k];
#pragma unroll 8
                    for (int i = 0; i < DIM; i++) {
                        float xi  = __shfl_sync(0xffffffffu, (i & 1) ? xA[q].y : xA[q].x, i >> 1);
                        float axi = a * xi;
                        fbA[q] += axi * M[i * DIM + l]      + xi * P[i * DIM + l];
                        fbB[q] += axi * M[i * DIM + 32 + l] + xi * P[i * DIM + 32 + l];
                    }
                }
            }
        }
#pragma unroll
        for (int q = 0; q < 4; q++) { mA[q] = mB[q]; mB[q] = mC[q]; xA[q] = xB[q]; }
    }

    // ---- stage S dim-major: sw[dim*16 + s*8 + {S1:0..3, S0:4..7}] ----
#pragma unroll
    for (int s = 0; s < MAXU; s++) {
        float x1[4], y1[4], x0[4], y0[4];
#pragma unroll
        for (int q = 0; q < 4; q++) {
            upk(S1p[s][q], x1[q], y1[q]);
            upk(S0p[s][q], x0[q], y0[q]);
        }
        *reinterpret_cast<float4*>(sw + (2 * l) * 16 + s * 8)         = make_float4(x1[0], x1[1], x1[2], x1[3]);
        *reinterpret_cast<float4*>(sw + (2 * l) * 16 + s * 8 + 4)     = make_float4(x0[0], x0[1], x0[2], x0[3]);
        *reinterpret_cast<float4*>(sw + (2 * l + 1) * 16 + s * 8)     = make_float4(y1[0], y1[1], y1[2], y1[3]);
        *reinterpret_cast<float4*>(sw + (2 * l + 1) * 16 + s * 8 + 4) = make_float4(y0[0], y0[1], y0[2], y0[3]);
    }
    __syncwarp();

    // ---- transform ----
    ull accA[2], accB[2];
    accA[0] = pk2(fbA[0], fbA[1]); accA[1] = pk2(fbA[2], fbA[3]);
    accB[0] = pk2(fbB[0], fbB[1]); accB[1] = pk2(fbB[2], fbB[3]);
#pragma unroll
    for (int s = 0; s < MAXU; s++) {
        if (s >= ns) break;
        const float4* __restrict__ Tk = reinterpret_cast<const float4*>(g_T[g_slotk[s]]);
#pragma unroll 4
        for (int i = 0; i < DIM; i++) {
            float4 sv1 = *reinterpret_cast<const float4*>(sw + i * 16 + s * 8);
            float4 sv0 = *reinterpret_cast<const float4*>(sw + i * 16 + s * 8 + 4);
            float4 tv  = __ldg(&Tk[i * 32 + l]);
            ull s1p01 = pk2(sv1.x, sv1.y), s1p23 = pk2(sv1.z, sv1.w);
            ull s0p01 = pk2(sv0.x, sv0.y), s0p23 = pk2(sv0.z, sv0.w);
            FMA_X2(accA[0], s1p01, pk2(tv.x, tv.x), accA[0]);
            FMA_X2(accA[1], s1p23, pk2(tv.x, tv.x), accA[1]);
            FMA_X2(accA[0], s0p01, pk2(tv.z, tv.z), accA[0]);
            FMA_X2(accA[1], s0p23, pk2(tv.z, tv.z), accA[1]);
            FMA_X2(accB[0], s1p01, pk2(tv.y, tv.y), accB[0]);
            FMA_X2(accB[1], s1p23, pk2(tv.y, tv.y), accB[1]);
            FMA_X2(accB[0], s0p01, pk2(tv.w, tv.w), accB[0]);
            FMA_X2(accB[1], s0p23, pk2(tv.w, tv.w), accB[1]);
        }
    }

    // ---- divide by counts ----
    {
        float i0 = __fdividef(1.0f, fmaxf((float)degv[0], 1.0f));
        float i1 = __fdividef(1.0f, fmaxf((float)degv[1], 1.0f));
        float i2 = __fdividef(1.0f, fmaxf((float)degv[2], 1.0f));
        float i3 = __fdividef(1.0f, fmaxf((float)degv[3], 1.0f));
        float v0, v1;
        upk(accA[0], v0, v1); accA[0] = pk2(v0 * i0, v1 * i1);
        upk(accA[1], v0, v1); accA[1] = pk2(v0 * i2, v1 * i3);
        upk(accB[0], v0, v1); accB[0] = pk2(v0 * i0, v1 * i1);
        upk(accB[1], v0, v1); accB[1] = pk2(v0 * i2, v1 * i3);
    }

    // ---- x_tgt pair-load + dim-major staging + conv root matvec ----
    float2 xtp[4];
#pragma unroll
    for (int q = 0; q < 4; q++)
        xtp[q] = *reinterpret_cast<const float2*>(g_h0 + (size_t)(t0 + q) * DIM + 2 * l);
    __syncwarp();
    *reinterpret_cast<float4*>(sw + (2 * l) * 4)     = make_float4(xtp[0].x, xtp[1].x, xtp[2].x, xtp[3].x);
    *reinterpret_cast<float4*>(sw + (2 * l + 1) * 4) = make_float4(xtp[0].y, xtp[1].y, xtp[2].y, xtp[3].y);
    __syncwarp();
#pragma unroll 4
    for (int i = 0; i < DIM; i++) {
        float4 xv = *reinterpret_cast<const float4*>(sw + i * 4);
        ulonglong2 wv = *reinterpret_cast<const ulonglong2*>(g_Wr_q + (i * 32 + l) * 2);
        ull xp01 = pk2(xv.x, xv.y), xp23 = pk2(xv.z, xv.w);
        FMA_X2(accA[0], xp01, wv.x, accA[0]); FMA_X2(accA[1], xp23, wv.x, accA[1]);
        FMA_X2(accB[0], xp01, wv.y, accB[0]); FMA_X2(accB[1], xp23, wv.y, accB[1]);
    }
    // x_tgt in l/32+l layout (for GRU h-init), read back from dim-major smem
    float xt0[4], xt1[4];
    {
        float4 v = *reinterpret_cast<const float4*>(sw + l * 4);
        xt0[0] = v.x; xt0[1] = v.y; xt0[2] = v.z; xt0[3] = v.w;
        float4 u = *reinterpret_cast<const float4*>(sw + (32 + l) * 4);
        xt1[0] = u.x; xt1[1] = u.y; xt1[2] = u.z; xt1[3] = u.w;
    }
    // m = relu(acc + b_conv) in l/32+l layout
    float m0[4], m1[4];
    {
        float bc0 = b_conv[l], bc1 = b_conv[32 + l];
        float v0, v1;
        upk(accA[0], v0, v1); m0[0] = fmaxf(v0 + bc0, 0.0f); m0[1] = fmaxf(v1 + bc0, 0.0f);
        upk(accA[1], v0, v1); m0[2] = fmaxf(v0 + bc0, 0.0f); m0[3] = fmaxf(v1 + bc0, 0.0f);
        upk(accB[0], v0, v1); m1[0] = fmaxf(v0 + bc1, 0.0f); m1[1] = fmaxf(v1 + bc1, 0.0f);
        upk(accB[1], v0, v1); m1[2] = fmaxf(v0 + bc1, 0.0f); m1[3] = fmaxf(v1 + bc1, 0.0f);
    }

    // ---- gi = m @ W_ih^T + b_ih ----
    __syncwarp();
    *reinterpret_cast<float4*>(sw + l * 4)        = make_float4(m0[0], m0[1], m0[2], m0[3]);
    *reinterpret_cast<float4*>(sw + (32 + l) * 4) = make_float4(m1[0], m1[1], m1[2], m1[3]);
    __syncwarp();
    ull gip[6][2];
#pragma unroll
    for (int t = 0; t < 6; t++) { gip[t][0] = 0ull; gip[t][1] = 0ull; }
#pragma unroll 2
    for (int o = 0; o < DIM; o++) {
        float4 mv = *reinterpret_cast<const float4*>(sw + o * 4);
        ull mp01 = pk2(mv.x, mv.y), mp23 = pk2(mv.z, mv.w);
#pragma unroll
        for (int tp = 0; tp < 3; tp++) {
            ulonglong2 wv = *reinterpret_cast<const ulonglong2*>(g_Wih_q + ((o * 3 + tp) * 32 + l) * 2);
            FMA_X2(gip[2 * tp][0],     mp01, wv.x, gip[2 * tp][0]);
            FMA_X2(gip[2 * tp][1],     mp23, wv.x, gip[2 * tp][1]);
            FMA_X2(gip[2 * tp + 1][0], mp01, wv.y, gip[2 * tp + 1][0]);
            FMA_X2(gip[2 * tp + 1][1], mp23, wv.y, gip[2 * tp + 1][1]);
        }
    }
    float gi[6][4];
#pragma unroll
    for (int t = 0; t < 6; t++) {
        float bi = b_ih[l + 32 * t];
        float v0, v1;
        upk(gip[t][0], v0, v1); gi[t][0] = v0 + bi; gi[t][1] = v1 + bi;
        upk(gip[t][1], v0, v1); gi[t][2] = v0 + bi; gi[t][3] = v1 + bi;
    }

    // ---- GRU x3 (h init = x_tgt) ----
    float h0r[4], h1r[4];
#pragma unroll
    for (int q = 0; q < 4; q++) { h0r[q] = xt0[q]; h1r[q] = xt1[q]; }
    float bh[6];
#pragma unroll
    for (int t = 0; t < 6; t++) bh[t] = b_hh[l + 32 * t];

    for (int step = 0; step < 3; step++) {
        __syncwarp();
        *reinterpret_cast<float4*>(sw + l * 4)        = make_float4(h0r[0], h0r[1], h0r[2], h0r[3]);
        *reinterpret_cast<float4*>(sw + (32 + l) * 4) = make_float4(h1r[0], h1r[1], h1r[2], h1r[3]);
        __syncwarp();
        ull ghp[6][2];
#pragma unroll
        for (int t = 0; t < 6; t++) {
            ghp[t][0] = pk2(bh[t], bh[t]);
            ghp[t][1] = ghp[t][0];
        }
#pragma unroll 2
        for (int i = 0; i < DIM; i++) {
            float4 hv = *reinterpret_cast<const float4*>(sw + i * 4);
            ull hp01 = pk2(hv.x, hv.y), hp23 = pk2(hv.z, hv.w);
#pragma unroll
            for (int tp = 0; tp < 3; tp++) {
                ulonglong2 wv = *reinterpret_cast<const ulonglong2*>(g_Whh_q + ((i * 3 + tp) * 32 + l) * 2);
                FMA_X2(ghp[2 * tp][0],     hp01, wv.x, ghp[2 * tp][0]);
                FMA_X2(ghp[2 * tp][1],     hp23, wv.x, ghp[2 * tp][1]);
                FMA_X2(ghp[2 * tp + 1][0], hp01, wv.y, ghp[2 * tp + 1][0]);
                FMA_X2(ghp[2 * tp + 1][1], hp23, wv.y, ghp[2 * tp + 1][1]);
            }
        }
#pragma unroll
        for (int q = 0; q < 4; q++) {
            float ghv[6];
#pragma unroll
            for (int t = 0; t < 6; t++) {
                float lo, hi;
                upk(ghp[t][q >> 1], lo, hi);
                ghv[t] = (q & 1) ? hi : lo;
            }
            float rr0 = sigm(gi[0][q] + ghv[0]);
            float rr1 = sigm(gi[1][q] + ghv[1]);
            float zz0 = sigm(gi[2][q] + ghv[2]);
            float zz1 = sigm(gi[3][q] + ghv[3]);
            float nn0 = tanhx(gi[4][q] + rr0 * ghv[4]);
            float nn1 = tanhx(gi[5][q] + rr1 * ghv[5]);
            h0r[q] = (1.0f - zz0) * nn0 + zz0 * h0r[q];
            h1r[q] = (1.0f - zz1) * nn1 + zz1 * h1r[q];
        }
    }

    // ---- head layer 1: a = relu(h @ W1^T + b1) ----
    __syncwarp();
    *reinterpret_cast<float4*>(sw + l * 4)        = make_float4(h0r[0], h0r[1], h0r[2], h0r[3]);
    *reinterpret_cast<float4*>(sw + (32 + l) * 4) = make_float4(h1r[0], h1r[1], h1r[2], h1r[3]);
    __syncwarp();
    ull aA01 = 0ull, aA23 = 0ull, aB01 = 0ull, aB23 = 0ull;
#pragma unroll 4
    for (int i = 0; i < DIM; i++) {
        float4 hv = *reinterpret_cast<const float4*>(sw + i * 4);
        ull hp01 = pk2(hv.x, hv.y), hp23 = pk2(hv.z, hv.w);
        ulonglong2 wv = *reinterpret_cast<const ulonglong2*>(g_W1q + (i * 32 + l) * 2);
        FMA_X2(aA01, hp01, wv.x, aA01); FMA_X2(aA23, hp23, wv.x, aA23);
        FMA_X2(aB01, hp01, wv.y, aB01); FMA_X2(aB23, hp23, wv.y, aB23);
    }
    float a0[4], a1[4];
    {
        float bb0 = b1[l], bb1 = b1[32 + l];
        float v0, v1;
        upk(aA01, v0, v1); a0[0] = fmaxf(v0 + bb0, 0.0f); a0[1] = fmaxf(v1 + bb0, 0.0f);
        upk(aA23, v0, v1); a0[2] = fmaxf(v0 + bb0, 0.0f); a0[3] = fmaxf(v1 + bb0, 0.0f);
        upk(aB01, v0, v1); a1[0] = fmaxf(v0 + bb1, 0.0f); a1[1] = fmaxf(v1 + bb1, 0.0f);
        upk(aB23, v0, v1); a1[2] = fmaxf(v0 + bb1, 0.0f); a1[3] = fmaxf(v1 + bb1, 0.0f);
    }

    // ---- head layer 2: out = a @ W2^T + b2 ----
    __syncwarp();
    *reinterpret_cast<float4*>(sw + l * 4)        = make_float4(a0[0], a0[1], a0[2], a0[3]);
    *reinterpret_cast<float4*>(sw + (32 + l) * 4) = make_float4(a1[0], a1[1], a1[2], a1[3]);
    __syncwarp();
    ull cA01 = 0ull, cA23 = 0ull, cB01 = 0ull, cB23 = 0ull;
#pragma unroll 4
    for (int i = 0; i < DIM; i++) {
        float4 av = *reinterpret_cast<const float4*>(sw + i * 4);
        ull ap01 = pk2(av.x, av.y), ap23 = pk2(av.z, av.w);
        ulonglong2 wv = *reinterpret_cast<const ulonglong2*>(g_W2q + (i * 32 + l) * 2);
        FMA_X2(cA01, ap01, wv.x, cA01); FMA_X2(cA23, ap23, wv.x, cA23);
        FMA_X2(cB01, ap01, wv.y, cB01); FMA_X2(cB23, ap23, wv.y, cB23);
    }
    {
        float ob0 = b2[l], ob1 = b2[32 + l];
        float v0, v1;
        upk(cA01, v0, v1);
        out[(size_t)(t0 + 0) * DIM + l] = v0 + ob0;
        out[(size_t)(t0 + 1) * DIM + l] = v1 + ob0;
        upk(cA23, v0, v1);
        out[(size_t)(t0 + 2) * DIM + l] = v0 + ob0;
        out[(size_t)(t0 + 3) * DIM + l] = v1 + ob0;
        upk(cB01, v0, v1);
        out[(size_t)(t0 + 0) * DIM + 32 + l] = v0 + ob1;
        out[(size_t)(t0 + 1) * DIM + 32 + l] = v1 + ob1;
        upk(cB23, v0, v1);
        out[(size_t)(t0 + 2) * DIM + 32 + l] = v0 + ob1;
        out[(size_t)(t0 + 3) * DIM + 32 + l] = v1 + ob1;
    }
}

// ---------------- launch ---------------------------------------------------
extern "C" void kernel_launch(void* const* d_in, const int* in_sizes, int n_in,
                              void* d_out, int out_size) {
    const float* x        = (const float*)d_in[0];
    const int*   edge_src = (const int*)d_in[2];
    const int*   edge_dst = (const int*)d_in[3];
    const int*   edge_ids = (const int*)d_in[4];
    const float* edge_w   = (const float*)d_in[5];
    const float* W0       = (const float*)d_in[6];
    const float* b0       = (const float*)d_in[7];
    const float* A1       = (const float*)d_in[8];
    const float* c1       = (const float*)d_in[9];
    const float* A2       = (const float*)d_in[10];
    const float* c2       = (const float*)d_in[11];
    const float* W_root   = (const float*)d_in[12];
    const float* b_conv   = (const float*)d_in[13];
    const float* W_ih     = (const float*)d_in[14];
    const float* W_hh     = (const float*)d_in[15];
    const float* b_ih     = (const float*)d_in[16];
    const float* b_hh     = (const float*)d_in[17];
    const float* W1       = (const float*)d_in[18];
    const float* b1       = (const float*)d_in[19];
    const float* W2       = (const float*)d_in[20];
    const float* b2       = (const float*)d_in[21];
    float* out = (float*)d_out;

    kA<<<128, 256>>>(W0, W_ih, W_hh, W_root, W1, W2, A1, c1);
    kB<<<H0_BLOCKS + 313, 256>>>(x, b0, edge_ids, edge_w, edge_dst);
    kC<<<2, 1024>>>();
    kD<<<CSR_BLOCKS + 512 * TB_Y, 256>>>(edge_src, edge_dst, A1, c1, A2, c2);
    k_tail<<<N_TGT / 4 / 8, 256>>>(b_conv, b_ih, b_hh, b1, b2, out);
}